// round 15
// baseline (speedup 1.0000x reference)
#include <cuda_runtime.h>
#include <cuda_fp16.h>
#include <math.h>

#define B_   4
#define Q_   64
#define H_   4096
#define NH_  32
#define KVH_ 8
#define HD_  128
#define P_   4096
#define M_   256            // B*Q
#define KVLEN 4160          // P+Q

// ---------------- scratch ----------------
__device__ float g_qraw [M_ * NH_ * HD_];
__device__ float g_qraw2[M_ * NH_ * HD_];
__device__ float g_kraw [M_ * KVH_ * HD_];
__device__ float g_kraw2[M_ * KVH_ * HD_];
__device__ float g_vraw [M_ * KVH_ * HD_];
__device__ float g_vraw2[M_ * KVH_ * HD_];
__device__ __half g_qh [B_ * NH_ * Q_ * HD_];     // Q fp16 (pre-scaled)
__device__ __half g_knh[B_ * KVH_ * Q_ * HD_];    // new K fp16, key-major
__device__ __half g_vnh[B_ * KVH_ * HD_ * Q_];    // new V fp16, d-major (transposed)
__device__ __half g_kh [B_ * KVH_ * P_ * HD_];    // past K fp16, key-major
__device__ __half g_vht[B_ * KVH_ * HD_ * P_];    // past V fp16, d-major (transposed)
__device__ float g_ctx[M_ * NH_ * HD_];
__device__ float g_actx[4 * B_ * NH_ * Q_ * HD_];
__device__ float g_am  [4 * B_ * NH_ * Q_];
__device__ float g_al  [4 * B_ * NH_ * Q_];

// ---------------- helpers ----------------
__device__ __forceinline__ unsigned f2u_tf32(float x) {
    unsigned r; asm("cvt.rna.tf32.f32 %0, %1;" : "=r"(r) : "f"(x)); return r;
}
__device__ __forceinline__ float f_tf32(float x) { return __uint_as_float(f2u_tf32(x)); }
__device__ __forceinline__ unsigned fu(float x) { return __float_as_uint(x); }
__device__ __forceinline__ unsigned rna_u(unsigned x) {
    unsigned r; asm("cvt.rna.tf32.f32 %0, %1;" : "=r"(r) : "f"(__uint_as_float(x))); return r;
}

__device__ __forceinline__ void mma_tf32(float& c0, float& c1, float& c2, float& c3,
                                         unsigned a0, unsigned a1, unsigned a2, unsigned a3,
                                         unsigned b0, unsigned b1) {
    asm volatile(
        "mma.sync.aligned.m16n8k8.row.col.f32.tf32.tf32.f32 "
        "{%0,%1,%2,%3}, {%4,%5,%6,%7}, {%8,%9}, {%0,%1,%2,%3};\n"
        : "+f"(c0), "+f"(c1), "+f"(c2), "+f"(c3)
        : "r"(a0), "r"(a1), "r"(a2), "r"(a3), "r"(b0), "r"(b1));
}

__device__ __forceinline__ void mma_f16(float& c0, float& c1, float& c2, float& c3,
                                        unsigned a0, unsigned a1, unsigned a2, unsigned a3,
                                        unsigned b0, unsigned b1) {
    asm volatile(
        "mma.sync.aligned.m16n8k16.row.col.f32.f16.f16.f32 "
        "{%0,%1,%2,%3}, {%4,%5,%6,%7}, {%8,%9}, {%0,%1,%2,%3};\n"
        : "+f"(c0), "+f"(c1), "+f"(c2), "+f"(c3)
        : "r"(a0), "r"(a1), "r"(a2), "r"(a3), "r"(b0), "r"(b1));
}

__device__ __forceinline__ void cp16(void* smem_dst, const void* gmem_src) {
    unsigned ds = (unsigned)__cvta_generic_to_shared(smem_dst);
    asm volatile("cp.async.cg.shared.global [%0], [%1], 16;\n" :: "r"(ds), "l"(gmem_src));
}
__device__ __forceinline__ unsigned pack_h2(float a, float b) {
    __half2 h = __floats2half2_rn(a, b);
    return *(unsigned*)&h;
}

// ================= pipelined tf32 GEMM: BM64 x BN128 x BK32, 256 thr, 3-stage =================
#define GA_S 36
#define GB_S 136
#define G_STAGE_FLOATS (64 * GA_S + 32 * GB_S)
#define GEMM_SMEM_FLOATS (3 * G_STAGE_FLOATS)
#define GEMM_SMEM_BYTES  (GEMM_SMEM_FLOATS * 4)

__device__ __forceinline__ void gemm_issue(
    const float* __restrict__ Abase, const float* __restrict__ Wbase,
    int lda, int N, int k0, float* sA, float* sB,
    int arow, int ac4, int brow, int bc4)
{
    cp16(sA + arow * GA_S + ac4,        Abase + arow * lda + k0 + ac4);
    cp16(sA + (arow + 32) * GA_S + ac4, Abase + (arow + 32) * lda + k0 + ac4);
    #pragma unroll
    for (int i = 0; i < 4; i++)
        cp16(sB + (brow + (i << 3)) * GB_S + bc4, Wbase + (k0 + brow + (i << 3)) * N + bc4);
    asm volatile("cp.async.commit_group;\n");
}

template<bool ATOMIC>
__device__ __forceinline__ void gemm_pipe(
    const float* __restrict__ A, int lda,
    const float* __restrict__ W, float* __restrict__ C,
    int N, int kLen, int m0, int n0, float* sm)
{
    float* sAs[3] = { sm, sm + G_STAGE_FLOATS, sm + 2 * G_STAGE_FLOATS };
    float* sBs[3] = { sm + 64 * GA_S, sm + G_STAGE_FLOATS + 64 * GA_S,
                      sm + 2 * G_STAGE_FLOATS + 64 * GA_S };

    const int tid = threadIdx.x;
    const int warp = tid >> 5, lane = tid & 31;
    const int mw = warp >> 2, nw = warp & 3;
    const int g = lane >> 2, t = lane & 3;

    const int arow = tid >> 3, ac4 = (tid & 7) << 2;
    const int brow = tid >> 5, bc4 = (tid & 31) << 2;

    const float* Abase = A + m0 * lda;
    const float* Wbase = W + n0;

    float acc[2][4][4];
    #pragma unroll
    for (int mt = 0; mt < 2; mt++)
        #pragma unroll
        for (int nt = 0; nt < 4; nt++)
            #pragma unroll
            for (int i = 0; i < 4; i++) acc[mt][nt][i] = 0.f;

    const int ntiles = kLen >> 5;
    gemm_issue(Abase, Wbase, lda, N, 0,  sAs[0], sBs[0], arow, ac4, brow, bc4);
    gemm_issue(Abase, Wbase, lda, N, 32, sAs[1], sBs[1], arow, ac4, brow, bc4);

    for (int tI = 0; tI < ntiles; tI++) {
        if (tI + 2 < ntiles) {
            gemm_issue(Abase, Wbase, lda, N, (tI + 2) << 5,
                       sAs[(tI + 2) % 3], sBs[(tI + 2) % 3], arow, ac4, brow, bc4);
            asm volatile("cp.async.wait_group 2;\n");
        } else if (tI + 1 < ntiles) {
            asm volatile("cp.async.wait_group 1;\n");
        } else {
            asm volatile("cp.async.wait_group 0;\n");
        }
        __syncthreads();

        float* sA = sAs[tI % 3];
        float* sB = sBs[tI % 3];

        #pragma unroll
        for (int ks = 0; ks < 4; ks++) {
            const int k0 = ks << 3;
            unsigned a[2][4], b[4][2];
            #pragma unroll
            for (int mt = 0; mt < 2; mt++) {
                const int r = (mw << 5) + (mt << 4) + g;
                a[mt][0] = rna_u(fu(sA[r * GA_S + k0 + t]));
                a[mt][1] = rna_u(fu(sA[(r + 8) * GA_S + k0 + t]));
                a[mt][2] = rna_u(fu(sA[r * GA_S + k0 + t + 4]));
                a[mt][3] = rna_u(fu(sA[(r + 8) * GA_S + k0 + t + 4]));
            }
            #pragma unroll
            for (int nt = 0; nt < 4; nt++) {
                const int cn = (nw << 5) + (nt << 3) + g;
                b[nt][0] = rna_u(fu(sB[(k0 + t) * GB_S + cn]));
                b[nt][1] = rna_u(fu(sB[(k0 + t + 4) * GB_S + cn]));
            }
            #pragma unroll
            for (int mt = 0; mt < 2; mt++)
                #pragma unroll
                for (int nt = 0; nt < 4; nt++)
                    mma_tf32(acc[mt][nt][0], acc[mt][nt][1], acc[mt][nt][2], acc[mt][nt][3],
                             a[mt][0], a[mt][1], a[mt][2], a[mt][3], b[nt][0], b[nt][1]);
        }
        __syncthreads();
    }

    #pragma unroll
    for (int mt = 0; mt < 2; mt++) {
        const int r = m0 + (mw << 5) + (mt << 4) + g;
        #pragma unroll
        for (int nt = 0; nt < 4; nt++) {
            const int cn = n0 + (nw << 5) + (nt << 3) + (t << 1);
            if (ATOMIC) {
                atomicAdd(C + r * N + cn,           acc[mt][nt][0]);
                atomicAdd(C + r * N + cn + 1,       acc[mt][nt][1]);
                atomicAdd(C + (r + 8) * N + cn,     acc[mt][nt][2]);
                atomicAdd(C + (r + 8) * N + cn + 1, acc[mt][nt][3]);
            } else {
                *(float2*)(C + r * N + cn)       = make_float2(acc[mt][nt][0], acc[mt][nt][1]);
                *(float2*)(C + (r + 8) * N + cn) = make_float2(acc[mt][nt][2], acc[mt][nt][3]);
            }
        }
    }
}

// fused QKV projection, split-K = 2 (partials summed in lnrope)
__global__ __launch_bounds__(256, 2) void gemm_qkv(
    const float* __restrict__ hs,
    const float* __restrict__ Wq, const float* __restrict__ Wk, const float* __restrict__ Wv,
    float* __restrict__ qraw, float* __restrict__ kraw, float* __restrict__ vraw,
    float* __restrict__ qraw2, float* __restrict__ kraw2, float* __restrict__ vraw2)
{
    extern __shared__ float smg[];
    const int x = blockIdx.x;
    const int kw = blockIdx.z;
    const float* W; float* C; int N, nb;
    if (x < 32)      { W = Wq; C = kw ? qraw2 : qraw; N = 4096; nb = x; }
    else if (x < 40) { W = Wk; C = kw ? kraw2 : kraw; N = 1024; nb = x - 32; }
    else             { W = Wv; C = kw ? vraw2 : vraw; N = 1024; nb = x - 40; }
    gemm_pipe<false>(hs + kw * 2048, H_, W + kw * 2048 * N, C, N, 2048,
                     blockIdx.y << 6, nb << 7, smg);
}

// out projection, split-K = 2, atomic accumulate into pre-zeroed out
__global__ __launch_bounds__(256, 2) void gemm_out(
    const float* __restrict__ A, const float* __restrict__ W, float* __restrict__ out)
{
    extern __shared__ float smg[];
    const int kw = blockIdx.z;
    const int KH = (NH_ * HD_) / 2;
    gemm_pipe<true>(A + kw * KH, NH_ * HD_, W + kw * KH * H_, out,
                    H_, KH, blockIdx.y << 6, blockIdx.x << 7, smg);
}

// ---------------- fp16 conversion kernels (run once, independent of QKV) ----------------
__global__ __launch_bounds__(256) void cvt_k(const float* __restrict__ src, __half* __restrict__ dst)
{
    const size_t i = ((size_t)blockIdx.x * 256 + threadIdx.x) << 3;
    const float4 a = *(const float4*)(src + i);
    const float4 b = *(const float4*)(src + i + 4);
    unsigned r0 = pack_h2(a.x, a.y), r1 = pack_h2(a.z, a.w);
    unsigned r2 = pack_h2(b.x, b.y), r3 = pack_h2(b.z, b.w);
    *(uint4*)(dst + i) = make_uint4(r0, r1, r2, r3);
}

__global__ __launch_bounds__(256) void cvt_vt(const float* __restrict__ v, __half* __restrict__ vt)
{
    __shared__ float tile[32][132];
    const int bk  = blockIdx.x >> 7;
    const int key0 = (blockIdx.x & 127) << 5;
    const int tid = threadIdx.x;

    const float* src = v + ((size_t)bk * P_ + key0) * HD_;
    const int row = tid >> 3, cb = (tid & 7) << 4;
    #pragma unroll
    for (int j = 0; j < 4; j++)
        *(float4*)&tile[row][cb + (j << 2)] = *(const float4*)(src + row * HD_ + cb + (j << 2));
    __syncthreads();

    const int d = tid >> 1, ks = (tid & 1) << 4;
    __half h[16];
    #pragma unroll
    for (int j = 0; j < 16; j++) h[j] = __float2half(tile[ks + j][d]);
    __half* dstp = vt + ((size_t)bk * HD_ + d) * P_ + key0 + ks;
    *(uint4*)(dstp)     = *(uint4*)&h[0];
    *(uint4*)(dstp + 8) = *(uint4*)&h[8];
}

// ---------------- LN + RoPE + transpose (sums split-K partials, emits fp16) ----------------
__global__ __launch_bounds__(128) void lnrope_kernel(
    const float* __restrict__ qraw, const float* __restrict__ qraw2,
    const float* __restrict__ kraw, const float* __restrict__ kraw2,
    const float* __restrict__ vraw, const float* __restrict__ vraw2,
    const float* __restrict__ qlw, const float* __restrict__ qlb,
    const float* __restrict__ klw, const float* __restrict__ klb,
    const int* __restrict__ pos_ids,
    __half* __restrict__ qout, __half* __restrict__ knout, __half* __restrict__ vnout)
{
    const int blk = blockIdx.x;
    const int bq = blk / 48;
    const int t  = blk - bq * 48;
    const int b  = bq >> 6, qi = bq & 63;
    const int d  = threadIdx.x;

    if (t >= 40) {
        const int vh = t - 40;
        const int i = bq * (KVH_ * HD_) + vh * HD_ + d;
        vnout[((b * KVH_ + vh) * HD_ + d) * Q_ + qi] = __float2half(vraw[i] + vraw2[i]);
        return;
    }

    __shared__ float row[128];
    __shared__ float red[4];

    float x, w, bb;
    const bool isq = (t < 32);
    if (isq) {
        const int i = bq * (NH_ * HD_) + t * HD_ + d;
        x  = qraw[i] + qraw2[i];
        w  = qlw[t * HD_ + d];
        bb = qlb[t * HD_ + d];
    } else {
        const int kh = t - 32;
        const int i = bq * (KVH_ * HD_) + kh * HD_ + d;
        x  = kraw[i] + kraw2[i];
        w  = klw[kh * HD_ + d];
        bb = klb[kh * HD_ + d];
    }

    const int lane = d & 31, wid = d >> 5;

    float s = x;
    #pragma unroll
    for (int o = 16; o; o >>= 1) s += __shfl_xor_sync(0xffffffffu, s, o);
    if (lane == 0) red[wid] = s;
    __syncthreads();
    const float mean = (red[0] + red[1] + red[2] + red[3]) * (1.f / 128.f);
    const float dx = x - mean;
    float s2 = dx * dx;
    __syncthreads();
    #pragma unroll
    for (int o = 16; o; o >>= 1) s2 += __shfl_xor_sync(0xffffffffu, s2, o);
    if (lane == 0) red[wid] = s2;
    __syncthreads();
    const float var = (red[0] + red[1] + red[2] + red[3]) * (1.f / 128.f);

    const float xn = dx * rsqrtf(var + 1e-5f) * w + bb;
    row[d] = xn;
    __syncthreads();
    const float partner = row[d ^ 64];

    const int j = d & 63;
    const float inv = (float)exp(-(double)(2 * j) * (1.0 / 128.0) * 9.210340371976184);
    const float ang = (float)pos_ids[b * Q_ + qi] * inv;
    const float c = cosf(ang), sn = sinf(ang);
    const float rot = (d < 64) ? -partner : partner;
    const float outv = xn * c + rot * sn;

    if (isq)
        qout[((b * NH_ + t) * Q_ + qi) * HD_ + d] = __float2half(outv * 0.08838834764831845f);
    else
        knout[((b * KVH_ + (t - 32)) * Q_ + qi) * HD_ + d] = __float2half(outv);
}

// ---------------- flash attention v8: fp16, 2 q-heads/CTA, 4-way KV split ----------------
// grid = (B*16 head-pairs, 4 splits), 256 threads = 8 warps (warps 0-3: head h0, 4-7: h0+1).
// Splits (chunk-aligned): starts {0,1056,2112,3136}, counts {33,33,32,32}.
#define CHK   32
#define SQ_H  136
#define SK_H  136
#define SVT_H 40
#define SP_H  40
#define POFF_Q   0
#define POFF_K0  (128 * SQ_H)                // 17408
#define POFF_K1  (POFF_K0 + CHK * SK_H)      // 21760
#define POFF_V0  (POFF_K1 + CHK * SK_H)      // 26112
#define POFF_V1  (POFF_V0 + HD_ * SVT_H)     // 31232
#define POFF_S   (POFF_V1 + HD_ * SVT_H)     // 36352
#define ATT8_HALFS (POFF_S + 128 * SP_H)     // 41472
#define ATT8_BYTES (ATT8_HALFS * 2)          // 82944

__global__ __launch_bounds__(256, 2) void attn_kernel8(
    const __half* __restrict__ kh, const __half* __restrict__ vht,
    const float* __restrict__ mask,
    const __half* __restrict__ qh, const __half* __restrict__ knh,
    const __half* __restrict__ vnh,
    float* __restrict__ actx, float* __restrict__ am, float* __restrict__ al)
{
    extern __shared__ __half smh[];
    __half* sQ  = smh + POFF_Q;
    __half* sKb[2] = { smh + POFF_K0, smh + POFF_K1 };
    __half* sVb[2] = { smh + POFF_V0, smh + POFF_V1 };
    __half* sS  = smh + POFF_S;

    const int tid = threadIdx.x;
    const int bp = blockIdx.x;           // b*16 + head_pair
    const int split = blockIdx.y;
    const int b = bp >> 4;
    const int h0 = (bp & 15) << 1;       // first head of the pair
    const int kvh = h0 >> 2;

    const int warp = tid >> 5, lane = tid & 31;
    const int g = lane >> 2, t = lane & 3;
    const int r0 = (warp << 4) + g;      // row in 0..127; head = r0>>6, qi = r0&63
    const int t2 = t << 1;
    const int hq = h0 + (r0 >> 6);       // this warp's head
    const int qi0 = r0 & 63;             // qi of first owned row (second is +8, same head)

    // loaders
    const int krow = tid >> 3, kcb = (tid & 7) << 4;   // K: 32 rows, 2 cp16/thread
    const int vrow = tid >> 1, vcb = (tid & 1) << 4;   // V: 128 rows, 2 cp16/thread

    // ---- load Q fp16 for both heads (128 x 128 halfs = 2048 uint4, 8/thread) ----
    {
        #pragma unroll
        for (int i = 0; i < 8; i++) {
            const int idx = tid + (i << 8);            // 0..2047
            const int row = idx >> 4, col = (idx & 15) << 3;
            const int hh = h0 + (row >> 6), qq = row & 63;
            *(uint4*)(sQ + row * SQ_H + col) =
                *(const uint4*)(qh + ((size_t)(b * NH_ + hh) * Q_ + qq) * HD_ + col);
        }
    }

    float m0r = -1e30f, m1r = -1e30f, l0r = 0.f, l1r = 0.f;

    float o[16][4];
    #pragma unroll
    for (int nt = 0; nt < 16; nt++)
        #pragma unroll
        for (int i = 0; i < 4; i++) o[nt][i] = 0.f;

    const int keybase0 = (split <= 1) ? split * 1056 : 2112 + (split - 2) * 1024;
    const int nchk = (split <= 1) ? 33 : 32;
    const size_t kbase_past = (size_t)(b * KVH_ + kvh) * P_ * HD_;
    const size_t kbase_new  = (size_t)(b * KVH_ + kvh) * Q_ * HD_;
    const size_t vbase_past = (size_t)(b * KVH_ + kvh) * HD_ * P_;
    const size_t vbase_new  = (size_t)(b * KVH_ + kvh) * HD_ * Q_;

    // prologue: issue chunk 0
    {
        const int base = keybase0;
        const __half* Kc = (base < P_) ? kh + kbase_past + (size_t)base * HD_
                                       : knh + kbase_new + (size_t)(base - P_) * HD_;
        const __half* Vc; int vstride;
        if (base < P_) { Vc = vht + vbase_past + base; vstride = P_; }
        else           { Vc = vnh + vbase_new + (base - P_); vstride = Q_; }
        cp16(sKb[0] + krow * SK_H + kcb,     Kc + krow * HD_ + kcb);
        cp16(sKb[0] + krow * SK_H + kcb + 8, Kc + krow * HD_ + kcb + 8);
        cp16(sVb[0] + vrow * SVT_H + vcb,     Vc + (size_t)vrow * vstride + vcb);
        cp16(sVb[0] + vrow * SVT_H + vcb + 8, Vc + (size_t)vrow * vstride + vcb + 8);
        asm volatile("cp.async.commit_group;\n");
    }

    // ---- hoist Q fragments (invariant across chunks) ----
    __syncthreads();
    unsigned qa[8][4];
    #pragma unroll
    for (int ks = 0; ks < 8; ks++) {
        const int k0 = ks << 4;
        qa[ks][0] = *(const unsigned*)&sQ[r0 * SQ_H + k0 + t2];
        qa[ks][1] = *(const unsigned*)&sQ[(r0 + 8) * SQ_H + k0 + t2];
        qa[ks][2] = *(const unsigned*)&sQ[r0 * SQ_H + k0 + 8 + t2];
        qa[ks][3] = *(const unsigned*)&sQ[(r0 + 8) * SQ_H + k0 + 8 + t2];
    }

    for (int chunk = 0; chunk < nchk; chunk++) {
        if (chunk + 1 < nchk) {
            const int base = keybase0 + (chunk + 1) * CHK;
            const __half* Kc = (base < P_) ? kh + kbase_past + (size_t)base * HD_
                                           : knh + kbase_new + (size_t)(base - P_) * HD_;
            const __half* Vc; int vstride;
            if (base < P_) { Vc = vht + vbase_past + base; vstride = P_; }
            else           { Vc = vnh + vbase_new + (base - P_); vstride = Q_; }
            __half* dK = sKb[(chunk + 1) & 1];
            __half* dV = sVb[(chunk + 1) & 1];
            cp16(dK + krow * SK_H + kcb,     Kc + krow * HD_ + kcb);
            cp16(dK + krow * SK_H + kcb + 8, Kc + krow * HD_ + kcb + 8);
            cp16(dV + vrow * SVT_H + vcb,     Vc + (size_t)vrow * vstride + vcb);
            cp16(dV + vrow * SVT_H + vcb + 8, Vc + (size_t)vrow * vstride + vcb + 8);
            asm volatile("cp.async.commit_group;\n");
            asm volatile("cp.async.wait_group 1;\n");
        } else {
            asm volatile("cp.async.wait_group 0;\n");
        }
        __syncthreads();

        __half* sK = sKb[chunk & 1];
        __half* sV = sVb[chunk & 1];

        // ---- S = Q K^T : warp tile 16x32 ----
        float sc[4][4];
        #pragma unroll
        for (int nt = 0; nt < 4; nt++)
            #pragma unroll
            for (int i = 0; i < 4; i++) sc[nt][i] = 0.f;

        #pragma unroll
        for (int ks = 0; ks < 8; ks++) {
            const int k0 = ks << 4;
            #pragma unroll
            for (int nt = 0; nt < 4; nt++) {
                const int cn = (nt << 3) + g;
                unsigned b0 = *(const unsigned*)&sK[cn * SK_H + k0 + t2];
                unsigned b1 = *(const unsigned*)&sK[cn * SK_H + k0 + 8 + t2];
                mma_f16(sc[nt][0], sc[nt][1], sc[nt][2], sc[nt][3],
                        qa[ks][0], qa[ks][1], qa[ks][2], qa[ks][3], b0, b1);
            }
        }

        // ---- mask (whole chunk masked iff base >= P_; mask independent of head) ----
        const int base = keybase0 + chunk * CHK;
        if (base >= P_) {
            const float* mr0 = mask + (b * Q_ + qi0) * KVLEN + base;
            const float* mr1 = mask + (b * Q_ + qi0 + 8) * KVLEN + base;
            #pragma unroll
            for (int nt = 0; nt < 4; nt++) {
                const float2 mv0 = *(const float2*)(mr0 + (nt << 3) + t2);
                const float2 mv1 = *(const float2*)(mr1 + (nt << 3) + t2);
                sc[nt][0] += mv0.x; sc[nt][1] += mv0.y;
                sc[nt][2] += mv1.x; sc[nt][3] += mv1.y;
            }
        }

        // ---- register softmax ----
        float cm0 = -1e30f, cm1 = -1e30f;
        #pragma unroll
        for (int nt = 0; nt < 4; nt++) {
            cm0 = fmaxf(cm0, fmaxf(sc[nt][0], sc[nt][1]));
            cm1 = fmaxf(cm1, fmaxf(sc[nt][2], sc[nt][3]));
        }
        cm0 = fmaxf(cm0, __shfl_xor_sync(0xffffffffu, cm0, 1));
        cm0 = fmaxf(cm0, __shfl_xor_sync(0xffffffffu, cm0, 2));
        cm1 = fmaxf(cm1, __shfl_xor_sync(0xffffffffu, cm1, 1));
        cm1 = fmaxf(cm1, __shfl_xor_sync(0xffffffffu, cm1, 2));

        const float mn0 = fmaxf(m0r, cm0);
        const float mn1 = fmaxf(m1r, cm1);
        const float scl0 = __expf(m0r - mn0);
        const float scl1 = __expf(m1r - mn1);

        float sum0 = 0.f, sum1 = 0.f;
        #pragma unroll
        for (int nt = 0; nt < 4; nt++) {
            float p;
            p = __expf(sc[nt][0] - mn0); sc[nt][0] = p; sum0 += p;
            p = __expf(sc[nt][1] - mn0); sc[nt][1] = p; sum0 += p;
            p = __expf(sc[nt][2] - mn1); sc[nt][2] = p; sum1 += p;
            p = __expf(sc[nt][3] - mn1); sc[nt][3] = p; sum1 += p;
        }
        sum0 += __shfl_xor_sync(0xffffffffu, sum0, 1);
        sum0 += __shfl_xor_sync(0xffffffffu, sum0, 2);
        sum1 += __shfl_xor_sync(0xffffffffu, sum1, 1);
        sum1 += __shfl_xor_sync(0xffffffffu, sum1, 2);

        l0r = l0r * scl0 + sum0;  m0r = mn0;
        l1r = l1r * scl1 + sum1;  m1r = mn1;

        // ---- rescale ctx frags ----
        #pragma unroll
        for (int nt = 0; nt < 16; nt++) {
            o[nt][0] *= scl0; o[nt][1] *= scl0;
            o[nt][2] *= scl1; o[nt][3] *= scl1;
        }

        // ---- store P fp16 (warp-local rows) ----
        #pragma unroll
        for (int nt = 0; nt < 4; nt++) {
            *(unsigned*)&sS[r0 * SP_H + (nt << 3) + t2]       = pack_h2(sc[nt][0], sc[nt][1]);
            *(unsigned*)&sS[(r0 + 8) * SP_H + (nt << 3) + t2] = pack_h2(sc[nt][2], sc[nt][3]);
        }
        __syncwarp();

        // ---- ctx += P @ V : 2 k16-steps x 16 nt ----
        #pragma unroll
        for (int kk = 0; kk < 2; kk++) {
            const int k0 = kk << 4;
            unsigned a0 = *(const unsigned*)&sS[r0 * SP_H + k0 + t2];
            unsigned a1 = *(const unsigned*)&sS[(r0 + 8) * SP_H + k0 + t2];
            unsigned a2 = *(const unsigned*)&sS[r0 * SP_H + k0 + 8 + t2];
            unsigned a3 = *(const unsigned*)&sS[(r0 + 8) * SP_H + k0 + 8 + t2];
            #pragma unroll
            for (int nt = 0; nt < 16; nt++) {
                const int cn = (nt << 3) + g;
                unsigned b0 = *(const unsigned*)&sV[cn * SVT_H + k0 + t2];
                unsigned b1 = *(const unsigned*)&sV[cn * SVT_H + k0 + 8 + t2];
                mma_f16(o[nt][0], o[nt][1], o[nt][2], o[nt][3], a0, a1, a2, a3, b0, b1);
            }
        }
        __syncthreads();
    }

    // ---- epilogue: write unnormalized acc + (m, l) ----
    const int bhq = b * NH_ + hq;
    float* abase = actx + ((size_t)(split * (B_ * NH_) + bhq) * Q_) * HD_;
    #pragma unroll
    for (int nt = 0; nt < 16; nt++) {
        const int cn = (nt << 3) + t2;
        *(float2*)(abase + qi0 * HD_ + cn)       = make_float2(o[nt][0], o[nt][1]);
        *(float2*)(abase + (qi0 + 8) * HD_ + cn) = make_float2(o[nt][2], o[nt][3]);
    }
    if (t == 0) {
        const int sidx = (split * (B_ * NH_) + bhq) * Q_;
        am[sidx + qi0]     = m0r;  al[sidx + qi0]     = l0r;
        am[sidx + qi0 + 8] = m1r;  al[sidx + qi0 + 8] = l1r;
    }
}

// merge the four attention splits -> ctx[b][qi][h][d]
__global__ __launch_bounds__(128) void attn_merge(
    const float* __restrict__ actx, const float* __restrict__ am,
    const float* __restrict__ al, float* __restrict__ ctx)
{
    const int bh = blockIdx.x;
    const int b = bh >> 5, h = bh & 31;
    const int d = threadIdx.x;
    const int q0 = blockIdx.y << 2;
    const int NBH = B_ * NH_;

    #pragma unroll
    for (int k = 0; k < 4; k++) {
        const int qi = q0 + k;
        float ms[4], ls[4];
        #pragma unroll
        for (int s = 0; s < 4; s++) {
            ms[s] = am[(s * NBH + bh) * Q_ + qi];
            ls[s] = al[(s * NBH + bh) * Q_ + qi];
        }
        float mm = fmaxf(fmaxf(ms[0], ms[1]), fmaxf(ms[2], ms[3]));
        float ws[4], den = 0.f;
        #pragma unroll
        for (int s = 0; s < 4; s++) { ws[s] = __expf(ms[s] - mm); den += ws[s] * ls[s]; }
        const float inv = 1.0f / den;
        float acc = 0.f;
        #pragma unroll
        for (int s = 0; s < 4; s++)
            acc += ws[s] * actx[((size_t)(s * NBH + bh) * Q_ + qi) * HD_ + d];
        ctx[((b * Q_ + qi) * NH_ + h) * HD_ + d] = acc * inv;
    }
}

// ---------------- launch ----------------
extern "C" void kernel_launch(void* const* d_in, const int* in_sizes, int n_in,
                              void* d_out, int out_size)
{
    const float* hs   = (const float*)d_in[0];
    const float* Wq   = (const float*)d_in[1];
    const float* Wk   = (const float*)d_in[2];
    const float* Wv   = (const float*)d_in[3];
    const float* Wo   = (const float*)d_in[4];
    const float* qlw  = (const float*)d_in[5];
    const float* qlb  = (const float*)d_in[6];
    const float* klw  = (const float*)d_in[7];
    const float* klb  = (const float*)d_in[8];
    const float* pk   = (const float*)d_in[9];
    const float* pv   = (const float*)d_in[10];
    const float* mask = (const float*)d_in[11];
    const int*   pos  = (const int*)d_in[12];
    float* out = (float*)d_out;

    float *qraw, *qraw2, *kraw, *kraw2, *vraw, *vraw2, *ctx, *actx, *am, *al;
    __half *qhp, *knhp, *vnhp, *khp, *vhtp;
    cudaGetSymbolAddress((void**)&qraw,  g_qraw);
    cudaGetSymbolAddress((void**)&qraw2, g_qraw2);
    cudaGetSymbolAddress((void**)&kraw,  g_kraw);
    cudaGetSymbolAddress((void**)&kraw2, g_kraw2);
    cudaGetSymbolAddress((void**)&vraw,  g_vraw);
    cudaGetSymbolAddress((void**)&vraw2, g_vraw2);
    cudaGetSymbolAddress((void**)&qhp,   g_qh);
    cudaGetSymbolAddress((void**)&knhp,  g_knh);
    cudaGetSymbolAddress((void**)&vnhp,  g_vnh);
    cudaGetSymbolAddress((void**)&khp,   g_kh);
    cudaGetSymbolAddress((void**)&vhtp,  g_vht);
    cudaGetSymbolAddress((void**)&ctx,   g_ctx);
    cudaGetSymbolAddress((void**)&actx,  g_actx);
    cudaGetSymbolAddress((void**)&am,    g_am);
    cudaGetSymbolAddress((void**)&al,    g_al);

    cudaFuncSetAttribute(attn_kernel8, cudaFuncAttributeMaxDynamicSharedMemorySize, ATT8_BYTES);
    cudaFuncSetAttribute(gemm_qkv,     cudaFuncAttributeMaxDynamicSharedMemorySize, GEMM_SMEM_BYTES);
    cudaFuncSetAttribute(gemm_out,     cudaFuncAttributeMaxDynamicSharedMemorySize, GEMM_SMEM_BYTES);

    // 0) one-shot fp16 conversion of past K/V (V transposed to d-major)
    cvt_k <<<(B_ * KVH_ * P_ * HD_) / (256 * 8), 256>>>(pk, khp);
    cvt_vt<<<B_ * KVH_ * (P_ / 32), 256>>>(pv, vhtp);

    // 1) fused QKV projection, split-K=2, 3-stage pipe
    gemm_qkv<<<dim3(48, 4, 2), 256, GEMM_SMEM_BYTES>>>(hs, Wq, Wk, Wv,
                                                       qraw, kraw, vraw, qraw2, kraw2, vraw2);

    // 2) LN + RoPE + transpose (+ split-K sum), fp16 outputs
    lnrope_kernel<<<M_ * 48, 128>>>(qraw, qraw2, kraw, kraw2, vraw, vraw2,
                                    qlw, qlb, klw, klb, pos, qhp, knhp, vnhp);

    // 3) attention: fp16, 2 heads/CTA (shared KV), 4-way split; then merge
    attn_kernel8<<<dim3(B_ * 16, 4), 256, ATT8_BYTES>>>(khp, vhtp, mask, qhp, knhp, vnhp,
                                                        actx, am, al);
    attn_merge<<<dim3(B_ * NH_, 16), 128>>>(actx, am, al, ctx);

    // 4) output projection: split-K=2, 3-stage pipe, atomic accumulate
    cudaMemsetAsync(out, 0, (size_t)M_ * H_ * sizeof(float));
    gemm_out<<<dim3(32, 4, 2), 256, GEMM_SMEM_BYTES>>>(ctx, Wo, out);
}

// round 16
// speedup vs baseline: 1.0673x; 1.0673x over previous
#include <cuda_runtime.h>
#include <cuda_fp16.h>
#include <math.h>

#define B_   4
#define Q_   64
#define H_   4096
#define NH_  32
#define KVH_ 8
#define HD_  128
#define P_   4096
#define M_   256            // B*Q
#define KVLEN 4160          // P+Q

// ---------------- scratch ----------------
__device__ float g_qraw [M_ * NH_ * HD_];
__device__ float g_qraw2[M_ * NH_ * HD_];
__device__ float g_kraw [M_ * KVH_ * HD_];
__device__ float g_kraw2[M_ * KVH_ * HD_];
__device__ float g_vraw [M_ * KVH_ * HD_];
__device__ float g_vraw2[M_ * KVH_ * HD_];
__device__ __half g_hsh[M_ * H_];                 // hidden_states fp16
__device__ __half g_wqt[H_ * (size_t)H_];         // Wq^T fp16 [n][k]
__device__ __half g_wkt[(KVH_ * HD_) * (size_t)H_]; // Wk^T fp16
__device__ __half g_wvt[(KVH_ * HD_) * (size_t)H_]; // Wv^T fp16
__device__ __half g_wot[H_ * (size_t)H_];         // Wo^T fp16
__device__ __half g_qh [B_ * NH_ * Q_ * HD_];     // Q fp16 (pre-scaled)
__device__ __half g_knh[B_ * KVH_ * Q_ * HD_];    // new K fp16, key-major
__device__ __half g_vnh[B_ * KVH_ * HD_ * Q_];    // new V fp16, d-major
__device__ __half g_kh [B_ * KVH_ * P_ * HD_];    // past K fp16, key-major
__device__ __half g_vht[B_ * KVH_ * HD_ * P_];    // past V fp16, d-major
__device__ __half g_ctxh[M_ * NH_ * HD_];         // ctx fp16 [b][qi][h][d]
__device__ float g_actx[4 * B_ * NH_ * Q_ * HD_];
__device__ float g_am  [4 * B_ * NH_ * Q_];
__device__ float g_al  [4 * B_ * NH_ * Q_];

// ---------------- helpers ----------------
__device__ __forceinline__ void mma_f16(float& c0, float& c1, float& c2, float& c3,
                                        unsigned a0, unsigned a1, unsigned a2, unsigned a3,
                                        unsigned b0, unsigned b1) {
    asm volatile(
        "mma.sync.aligned.m16n8k16.row.col.f32.f16.f16.f32 "
        "{%0,%1,%2,%3}, {%4,%5,%6,%7}, {%8,%9}, {%0,%1,%2,%3};\n"
        : "+f"(c0), "+f"(c1), "+f"(c2), "+f"(c3)
        : "r"(a0), "r"(a1), "r"(a2), "r"(a3), "r"(b0), "r"(b1));
}

__device__ __forceinline__ void cp16(void* smem_dst, const void* gmem_src) {
    unsigned ds = (unsigned)__cvta_generic_to_shared(smem_dst);
    asm volatile("cp.async.cg.shared.global [%0], [%1], 16;\n" :: "r"(ds), "l"(gmem_src));
}
__device__ __forceinline__ unsigned pack_h2(float a, float b) {
    __half2 h = __floats2half2_rn(a, b);
    return *(unsigned*)&h;
}

// ================= fp16 GEMM: BM64 x BN128 x BK32, 256 thr, 3-stage, m16n8k16 =================
#define HA_S 40                                   // halfs; frag banks g*20+t distinct
#define HB_S 40
#define H_STAGE (64 * HA_S + 128 * HB_S)          // 7680 halfs
#define GEMMH_SMEM_BYTES (3 * H_STAGE * 2)        // 46080

template<bool ATOMIC>
__device__ __forceinline__ void gemm_h(
    const __half* __restrict__ A, int lda,
    const __half* __restrict__ Wt, int ldw,
    float* __restrict__ C, int N, int kLen, int m0, int n0, __half* sm)
{
    __half* sAs[3] = { sm, sm + H_STAGE, sm + 2 * H_STAGE };
    __half* sBs[3] = { sm + 64 * HA_S, sm + H_STAGE + 64 * HA_S,
                       sm + 2 * H_STAGE + 64 * HA_S };

    const int tid = threadIdx.x;
    const int warp = tid >> 5, lane = tid & 31;
    const int mw = warp >> 2, nw = warp & 3;
    const int g = lane >> 2, t = lane & 3;
    const int t2 = t << 1;

    const int arow = tid >> 2, acb = (tid & 3) << 3;    // A: 64 rows x 4 cp16
    const int brow = tid >> 1, bcb = (tid & 1) << 4;    // B: 128 rows x 2x(2 cp16)

    const __half* Abase = A + (size_t)m0 * lda;
    const __half* Wbase = Wt + (size_t)n0 * ldw;

    float acc[2][4][4];
    #pragma unroll
    for (int mt = 0; mt < 2; mt++)
        #pragma unroll
        for (int nt = 0; nt < 4; nt++)
            #pragma unroll
            for (int i = 0; i < 4; i++) acc[mt][nt][i] = 0.f;

    const int ntiles = kLen >> 5;

    #define GISSUE(k0, sA, sB) do { \
        cp16((sA) + arow * HA_S + acb, Abase + (size_t)arow * lda + (k0) + acb); \
        cp16((sB) + brow * HB_S + bcb,     Wbase + (size_t)brow * ldw + (k0) + bcb); \
        cp16((sB) + brow * HB_S + bcb + 8, Wbase + (size_t)brow * ldw + (k0) + bcb + 8); \
        asm volatile("cp.async.commit_group;\n"); \
    } while (0)

    GISSUE(0,  sAs[0], sBs[0]);
    GISSUE(32, sAs[1], sBs[1]);

    for (int tI = 0; tI < ntiles; tI++) {
        if (tI + 2 < ntiles) {
            GISSUE((tI + 2) << 5, sAs[(tI + 2) % 3], sBs[(tI + 2) % 3]);
            asm volatile("cp.async.wait_group 2;\n");
        } else if (tI + 1 < ntiles) {
            asm volatile("cp.async.wait_group 1;\n");
        } else {
            asm volatile("cp.async.wait_group 0;\n");
        }
        __syncthreads();

        __half* sA = sAs[tI % 3];
        __half* sB = sBs[tI % 3];

        #pragma unroll
        for (int ks = 0; ks < 2; ks++) {
            const int k0 = ks << 4;
            unsigned a[2][4], b[4][2];
            #pragma unroll
            for (int mt = 0; mt < 2; mt++) {
                const int r = (mw << 5) + (mt << 4) + g;
                a[mt][0] = *(const unsigned*)&sA[r * HA_S + k0 + t2];
                a[mt][1] = *(const unsigned*)&sA[(r + 8) * HA_S + k0 + t2];
                a[mt][2] = *(const unsigned*)&sA[r * HA_S + k0 + 8 + t2];
                a[mt][3] = *(const unsigned*)&sA[(r + 8) * HA_S + k0 + 8 + t2];
            }
            #pragma unroll
            for (int nt = 0; nt < 4; nt++) {
                const int cn = (nw << 5) + (nt << 3) + g;
                b[nt][0] = *(const unsigned*)&sB[cn * HB_S + k0 + t2];
                b[nt][1] = *(const unsigned*)&sB[cn * HB_S + k0 + 8 + t2];
            }
            #pragma unroll
            for (int mt = 0; mt < 2; mt++)
                #pragma unroll
                for (int nt = 0; nt < 4; nt++)
                    mma_f16(acc[mt][nt][0], acc[mt][nt][1], acc[mt][nt][2], acc[mt][nt][3],
                            a[mt][0], a[mt][1], a[mt][2], a[mt][3], b[nt][0], b[nt][1]);
        }
        __syncthreads();
    }
    #undef GISSUE

    #pragma unroll
    for (int mt = 0; mt < 2; mt++) {
        const int r = m0 + (mw << 5) + (mt << 4) + g;
        #pragma unroll
        for (int nt = 0; nt < 4; nt++) {
            const int cn = n0 + (nw << 5) + (nt << 3) + (t << 1);
            if (ATOMIC) {
                atomicAdd(C + r * N + cn,           acc[mt][nt][0]);
                atomicAdd(C + r * N + cn + 1,       acc[mt][nt][1]);
                atomicAdd(C + (r + 8) * N + cn,     acc[mt][nt][2]);
                atomicAdd(C + (r + 8) * N + cn + 1, acc[mt][nt][3]);
            } else {
                *(float2*)(C + r * N + cn)       = make_float2(acc[mt][nt][0], acc[mt][nt][1]);
                *(float2*)(C + (r + 8) * N + cn) = make_float2(acc[mt][nt][2], acc[mt][nt][3]);
            }
        }
    }
}

// fused QKV projection (fp16), split-K = 2 (partials summed in lnrope)
__global__ __launch_bounds__(256, 2) void gemm_qkv(
    const __half* __restrict__ hsh,
    const __half* __restrict__ wqt, const __half* __restrict__ wkt, const __half* __restrict__ wvt,
    float* __restrict__ qraw, float* __restrict__ kraw, float* __restrict__ vraw,
    float* __restrict__ qraw2, float* __restrict__ kraw2, float* __restrict__ vraw2)
{
    extern __shared__ __half smh[];
    const int x = blockIdx.x;
    const int kw = blockIdx.z;
    const __half* Wt; float* C; int N, nb;
    if (x < 32)      { Wt = wqt; C = kw ? qraw2 : qraw; N = 4096; nb = x; }
    else if (x < 40) { Wt = wkt; C = kw ? kraw2 : kraw; N = 1024; nb = x - 32; }
    else             { Wt = wvt; C = kw ? vraw2 : vraw; N = 1024; nb = x - 40; }
    gemm_h<false>(hsh + kw * 2048, H_, Wt + kw * 2048, H_, C, N, 2048,
                  blockIdx.y << 6, nb << 7, smh);
}

// out projection (fp16), split-K = 2, atomic accumulate into pre-zeroed out
__global__ __launch_bounds__(256, 2) void gemm_out(
    const __half* __restrict__ ctxh, const __half* __restrict__ wot, float* __restrict__ out)
{
    extern __shared__ __half smh[];
    const int kw = blockIdx.z;
    const int KH = (NH_ * HD_) / 2;   // 2048
    gemm_h<true>(ctxh + kw * KH, NH_ * HD_, wot + kw * KH, NH_ * HD_, out,
                 H_, KH, blockIdx.y << 6, blockIdx.x << 7, smh);
}

// ---------------- fp16 conversion kernels (one-shot) ----------------
__global__ __launch_bounds__(256) void cvt_elem(const float* __restrict__ src, __half* __restrict__ dst)
{
    const size_t i = ((size_t)blockIdx.x * 256 + threadIdx.x) << 3;
    const float4 a = *(const float4*)(src + i);
    const float4 b = *(const float4*)(src + i + 4);
    *(uint4*)(dst + i) = make_uint4(pack_h2(a.x, a.y), pack_h2(a.z, a.w),
                                    pack_h2(b.x, b.y), pack_h2(b.z, b.w));
}

// transpose+convert: src fp32 [K][N] -> dst fp16 [N][K]. grid (N/128, K/32).
__global__ __launch_bounds__(256) void cvt_wt(const float* __restrict__ src, __half* __restrict__ dst,
                                              int N, int K)
{
    __shared__ float tile[32][132];
    const int n0 = blockIdx.x << 7, k0 = blockIdx.y << 5;
    const int tid = threadIdx.x;

    const int row = tid >> 3, cb = (tid & 7) << 4;
    #pragma unroll
    for (int j = 0; j < 4; j++)
        *(float4*)&tile[row][cb + (j << 2)] =
            *(const float4*)(src + (size_t)(k0 + row) * N + n0 + cb + (j << 2));
    __syncthreads();

    const int n = tid >> 1, ks = (tid & 1) << 4;
    __half h[16];
    #pragma unroll
    for (int j = 0; j < 16; j++) h[j] = __float2half(tile[ks + j][n]);
    __half* dstp = dst + (size_t)(n0 + n) * K + k0 + ks;
    *(uint4*)(dstp)     = *(uint4*)&h[0];
    *(uint4*)(dstp + 8) = *(uint4*)&h[8];
}

// past_v transpose (key-major -> d-major), as R15
__global__ __launch_bounds__(256) void cvt_vt(const float* __restrict__ v, __half* __restrict__ vt)
{
    __shared__ float tile[32][132];
    const int bk  = blockIdx.x >> 7;
    const int key0 = (blockIdx.x & 127) << 5;
    const int tid = threadIdx.x;

    const float* src = v + ((size_t)bk * P_ + key0) * HD_;
    const int row = tid >> 3, cb = (tid & 7) << 4;
    #pragma unroll
    for (int j = 0; j < 4; j++)
        *(float4*)&tile[row][cb + (j << 2)] = *(const float4*)(src + row * HD_ + cb + (j << 2));
    __syncthreads();

    const int d = tid >> 1, ks = (tid & 1) << 4;
    __half h[16];
    #pragma unroll
    for (int j = 0; j < 16; j++) h[j] = __float2half(tile[ks + j][d]);
    __half* dstp = vt + ((size_t)bk * HD_ + d) * P_ + key0 + ks;
    *(uint4*)(dstp)     = *(uint4*)&h[0];
    *(uint4*)(dstp + 8) = *(uint4*)&h[8];
}

// ---------------- LN + RoPE + transpose (sums split-K partials, emits fp16) ----------------
__global__ __launch_bounds__(128) void lnrope_kernel(
    const float* __restrict__ qraw, const float* __restrict__ qraw2,
    const float* __restrict__ kraw, const float* __restrict__ kraw2,
    const float* __restrict__ vraw, const float* __restrict__ vraw2,
    const float* __restrict__ qlw, const float* __restrict__ qlb,
    const float* __restrict__ klw, const float* __restrict__ klb,
    const int* __restrict__ pos_ids,
    __half* __restrict__ qout, __half* __restrict__ knout, __half* __restrict__ vnout)
{
    const int blk = blockIdx.x;
    const int bq = blk / 48;
    const int t  = blk - bq * 48;
    const int b  = bq >> 6, qi = bq & 63;
    const int d  = threadIdx.x;

    if (t >= 40) {
        const int vh = t - 40;
        const int i = bq * (KVH_ * HD_) + vh * HD_ + d;
        vnout[((b * KVH_ + vh) * HD_ + d) * Q_ + qi] = __float2half(vraw[i] + vraw2[i]);
        return;
    }

    __shared__ float row[128];
    __shared__ float red[4];

    float x, w, bb;
    const bool isq = (t < 32);
    if (isq) {
        const int i = bq * (NH_ * HD_) + t * HD_ + d;
        x  = qraw[i] + qraw2[i];
        w  = qlw[t * HD_ + d];
        bb = qlb[t * HD_ + d];
    } else {
        const int kh = t - 32;
        const int i = bq * (KVH_ * HD_) + kh * HD_ + d;
        x  = kraw[i] + kraw2[i];
        w  = klw[kh * HD_ + d];
        bb = klb[kh * HD_ + d];
    }

    const int lane = d & 31, wid = d >> 5;

    float s = x;
    #pragma unroll
    for (int o = 16; o; o >>= 1) s += __shfl_xor_sync(0xffffffffu, s, o);
    if (lane == 0) red[wid] = s;
    __syncthreads();
    const float mean = (red[0] + red[1] + red[2] + red[3]) * (1.f / 128.f);
    const float dx = x - mean;
    float s2 = dx * dx;
    __syncthreads();
    #pragma unroll
    for (int o = 16; o; o >>= 1) s2 += __shfl_xor_sync(0xffffffffu, s2, o);
    if (lane == 0) red[wid] = s2;
    __syncthreads();
    const float var = (red[0] + red[1] + red[2] + red[3]) * (1.f / 128.f);

    const float xn = dx * rsqrtf(var + 1e-5f) * w + bb;
    row[d] = xn;
    __syncthreads();
    const float partner = row[d ^ 64];

    const int j = d & 63;
    const float inv = (float)exp(-(double)(2 * j) * (1.0 / 128.0) * 9.210340371976184);
    const float ang = (float)pos_ids[b * Q_ + qi] * inv;
    const float c = cosf(ang), sn = sinf(ang);
    const float rot = (d < 64) ? -partner : partner;
    const float outv = xn * c + rot * sn;

    if (isq)
        qout[((b * NH_ + t) * Q_ + qi) * HD_ + d] = __float2half(outv * 0.08838834764831845f);
    else
        knout[((b * KVH_ + (t - 32)) * Q_ + qi) * HD_ + d] = __float2half(outv);
}

// ---------------- flash attention v8 (R15): fp16, 2 q-heads/CTA, 4-way KV split ----------------
#define CHK   32
#define SQ_H  136
#define SK_H  136
#define SVT_H 40
#define SP_H  40
#define POFF_Q   0
#define POFF_K0  (128 * SQ_H)
#define POFF_K1  (POFF_K0 + CHK * SK_H)
#define POFF_V0  (POFF_K1 + CHK * SK_H)
#define POFF_V1  (POFF_V0 + HD_ * SVT_H)
#define POFF_S   (POFF_V1 + HD_ * SVT_H)
#define ATT8_HALFS (POFF_S + 128 * SP_H)
#define ATT8_BYTES (ATT8_HALFS * 2)

__global__ __launch_bounds__(256, 2) void attn_kernel8(
    const __half* __restrict__ kh, const __half* __restrict__ vht,
    const float* __restrict__ mask,
    const __half* __restrict__ qh, const __half* __restrict__ knh,
    const __half* __restrict__ vnh,
    float* __restrict__ actx, float* __restrict__ am, float* __restrict__ al)
{
    extern __shared__ __half smh[];
    __half* sQ  = smh + POFF_Q;
    __half* sKb[2] = { smh + POFF_K0, smh + POFF_K1 };
    __half* sVb[2] = { smh + POFF_V0, smh + POFF_V1 };
    __half* sS  = smh + POFF_S;

    const int tid = threadIdx.x;
    const int bp = blockIdx.x;
    const int split = blockIdx.y;
    const int b = bp >> 4;
    const int h0 = (bp & 15) << 1;
    const int kvh = h0 >> 2;

    const int warp = tid >> 5, lane = tid & 31;
    const int g = lane >> 2, t = lane & 3;
    const int r0 = (warp << 4) + g;
    const int t2 = t << 1;
    const int hq = h0 + (r0 >> 6);
    const int qi0 = r0 & 63;

    const int krow = tid >> 3, kcb = (tid & 7) << 4;
    const int vrow = tid >> 1, vcb = (tid & 1) << 4;

    {
        #pragma unroll
        for (int i = 0; i < 8; i++) {
            const int idx = tid + (i << 8);
            const int row = idx >> 4, col = (idx & 15) << 3;
            const int hh = h0 + (row >> 6), qq = row & 63;
            *(uint4*)(sQ + row * SQ_H + col) =
                *(const uint4*)(qh + ((size_t)(b * NH_ + hh) * Q_ + qq) * HD_ + col);
        }
    }

    float m0r = -1e30f, m1r = -1e30f, l0r = 0.f, l1r = 0.f;

    float o[16][4];
    #pragma unroll
    for (int nt = 0; nt < 16; nt++)
        #pragma unroll
        for (int i = 0; i < 4; i++) o[nt][i] = 0.f;

    const int keybase0 = (split <= 1) ? split * 1056 : 2112 + (split - 2) * 1024;
    const int nchk = (split <= 1) ? 33 : 32;
    const size_t kbase_past = (size_t)(b * KVH_ + kvh) * P_ * HD_;
    const size_t kbase_new  = (size_t)(b * KVH_ + kvh) * Q_ * HD_;
    const size_t vbase_past = (size_t)(b * KVH_ + kvh) * HD_ * P_;
    const size_t vbase_new  = (size_t)(b * KVH_ + kvh) * HD_ * Q_;

    {
        const int base = keybase0;
        const __half* Kc = (base < P_) ? kh + kbase_past + (size_t)base * HD_
                                       : knh + kbase_new + (size_t)(base - P_) * HD_;
        const __half* Vc; int vstride;
        if (base < P_) { Vc = vht + vbase_past + base; vstride = P_; }
        else           { Vc = vnh + vbase_new + (base - P_); vstride = Q_; }
        cp16(sKb[0] + krow * SK_H + kcb,     Kc + krow * HD_ + kcb);
        cp16(sKb[0] + krow * SK_H + kcb + 8, Kc + krow * HD_ + kcb + 8);
        cp16(sVb[0] + vrow * SVT_H + vcb,     Vc + (size_t)vrow * vstride + vcb);
        cp16(sVb[0] + vrow * SVT_H + vcb + 8, Vc + (size_t)vrow * vstride + vcb + 8);
        asm volatile("cp.async.commit_group;\n");
    }

    __syncthreads();
    unsigned qa[8][4];
    #pragma unroll
    for (int ks = 0; ks < 8; ks++) {
        const int k0 = ks << 4;
        qa[ks][0] = *(const unsigned*)&sQ[r0 * SQ_H + k0 + t2];
        qa[ks][1] = *(const unsigned*)&sQ[(r0 + 8) * SQ_H + k0 + t2];
        qa[ks][2] = *(const unsigned*)&sQ[r0 * SQ_H + k0 + 8 + t2];
        qa[ks][3] = *(const unsigned*)&sQ[(r0 + 8) * SQ_H + k0 + 8 + t2];
    }

    for (int chunk = 0; chunk < nchk; chunk++) {
        if (chunk + 1 < nchk) {
            const int base = keybase0 + (chunk + 1) * CHK;
            const __half* Kc = (base < P_) ? kh + kbase_past + (size_t)base * HD_
                                           : knh + kbase_new + (size_t)(base - P_) * HD_;
            const __half* Vc; int vstride;
            if (base < P_) { Vc = vht + vbase_past + base; vstride = P_; }
            else           { Vc = vnh + vbase_new + (base - P_); vstride = Q_; }
            __half* dK = sKb[(chunk + 1) & 1];
            __half* dV = sVb[(chunk + 1) & 1];
            cp16(dK + krow * SK_H + kcb,     Kc + krow * HD_ + kcb);
            cp16(dK + krow * SK_H + kcb + 8, Kc + krow * HD_ + kcb + 8);
            cp16(dV + vrow * SVT_H + vcb,     Vc + (size_t)vrow * vstride + vcb);
            cp16(dV + vrow * SVT_H + vcb + 8, Vc + (size_t)vrow * vstride + vcb + 8);
            asm volatile("cp.async.commit_group;\n");
            asm volatile("cp.async.wait_group 1;\n");
        } else {
            asm volatile("cp.async.wait_group 0;\n");
        }
        __syncthreads();

        __half* sK = sKb[chunk & 1];
        __half* sV = sVb[chunk & 1];

        float sc[4][4];
        #pragma unroll
        for (int nt = 0; nt < 4; nt++)
            #pragma unroll
            for (int i = 0; i < 4; i++) sc[nt][i] = 0.f;

        #pragma unroll
        for (int ks = 0; ks < 8; ks++) {
            const int k0 = ks << 4;
            #pragma unroll
            for (int nt = 0; nt < 4; nt++) {
                const int cn = (nt << 3) + g;
                unsigned b0 = *(const unsigned*)&sK[cn * SK_H + k0 + t2];
                unsigned b1 = *(const unsigned*)&sK[cn * SK_H + k0 + 8 + t2];
                mma_f16(sc[nt][0], sc[nt][1], sc[nt][2], sc[nt][3],
                        qa[ks][0], qa[ks][1], qa[ks][2], qa[ks][3], b0, b1);
            }
        }

        const int base = keybase0 + chunk * CHK;
        if (base >= P_) {
            const float* mr0 = mask + (b * Q_ + qi0) * KVLEN + base;
            const float* mr1 = mask + (b * Q_ + qi0 + 8) * KVLEN + base;
            #pragma unroll
            for (int nt = 0; nt < 4; nt++) {
                const float2 mv0 = *(const float2*)(mr0 + (nt << 3) + t2);
                const float2 mv1 = *(const float2*)(mr1 + (nt << 3) + t2);
                sc[nt][0] += mv0.x; sc[nt][1] += mv0.y;
                sc[nt][2] += mv1.x; sc[nt][3] += mv1.y;
            }
        }

        float cm0 = -1e30f, cm1 = -1e30f;
        #pragma unroll
        for (int nt = 0; nt < 4; nt++) {
            cm0 = fmaxf(cm0, fmaxf(sc[nt][0], sc[nt][1]));
            cm1 = fmaxf(cm1, fmaxf(sc[nt][2], sc[nt][3]));
        }
        cm0 = fmaxf(cm0, __shfl_xor_sync(0xffffffffu, cm0, 1));
        cm0 = fmaxf(cm0, __shfl_xor_sync(0xffffffffu, cm0, 2));
        cm1 = fmaxf(cm1, __shfl_xor_sync(0xffffffffu, cm1, 1));
        cm1 = fmaxf(cm1, __shfl_xor_sync(0xffffffffu, cm1, 2));

        const float mn0 = fmaxf(m0r, cm0);
        const float mn1 = fmaxf(m1r, cm1);
        const float scl0 = __expf(m0r - mn0);
        const float scl1 = __expf(m1r - mn1);

        float sum0 = 0.f, sum1 = 0.f;
        #pragma unroll
        for (int nt = 0; nt < 4; nt++) {
            float p;
            p = __expf(sc[nt][0] - mn0); sc[nt][0] = p; sum0 += p;
            p = __expf(sc[nt][1] - mn0); sc[nt][1] = p; sum0 += p;
            p = __expf(sc[nt][2] - mn1); sc[nt][2] = p; sum1 += p;
            p = __expf(sc[nt][3] - mn1); sc[nt][3] = p; sum1 += p;
        }
        sum0 += __shfl_xor_sync(0xffffffffu, sum0, 1);
        sum0 += __shfl_xor_sync(0xffffffffu, sum0, 2);
        sum1 += __shfl_xor_sync(0xffffffffu, sum1, 1);
        sum1 += __shfl_xor_sync(0xffffffffu, sum1, 2);

        l0r = l0r * scl0 + sum0;  m0r = mn0;
        l1r = l1r * scl1 + sum1;  m1r = mn1;

        #pragma unroll
        for (int nt = 0; nt < 16; nt++) {
            o[nt][0] *= scl0; o[nt][1] *= scl0;
            o[nt][2] *= scl1; o[nt][3] *= scl1;
        }

        #pragma unroll
        for (int nt = 0; nt < 4; nt++) {
            *(unsigned*)&sS[r0 * SP_H + (nt << 3) + t2]       = pack_h2(sc[nt][0], sc[nt][1]);
            *(unsigned*)&sS[(r0 + 8) * SP_H + (nt << 3) + t2] = pack_h2(sc[nt][2], sc[nt][3]);
        }
        __syncwarp();

        #pragma unroll
        for (int kk = 0; kk < 2; kk++) {
            const int k0 = kk << 4;
            unsigned a0 = *(const unsigned*)&sS[r0 * SP_H + k0 + t2];
            unsigned a1 = *(const unsigned*)&sS[(r0 + 8) * SP_H + k0 + t2];
            unsigned a2 = *(const unsigned*)&sS[r0 * SP_H + k0 + 8 + t2];
            unsigned a3 = *(const unsigned*)&sS[(r0 + 8) * SP_H + k0 + 8 + t2];
            #pragma unroll
            for (int nt = 0; nt < 16; nt++) {
                const int cn = (nt << 3) + g;
                unsigned b0 = *(const unsigned*)&sV[cn * SVT_H + k0 + t2];
                unsigned b1 = *(const unsigned*)&sV[cn * SVT_H + k0 + 8 + t2];
                mma_f16(o[nt][0], o[nt][1], o[nt][2], o[nt][3], a0, a1, a2, a3, b0, b1);
            }
        }
        __syncthreads();
    }

    const int bhq = b * NH_ + hq;
    float* abase = actx + ((size_t)(split * (B_ * NH_) + bhq) * Q_) * HD_;
    #pragma unroll
    for (int nt = 0; nt < 16; nt++) {
        const int cn = (nt << 3) + t2;
        *(float2*)(abase + qi0 * HD_ + cn)       = make_float2(o[nt][0], o[nt][1]);
        *(float2*)(abase + (qi0 + 8) * HD_ + cn) = make_float2(o[nt][2], o[nt][3]);
    }
    if (t == 0) {
        const int sidx = (split * (B_ * NH_) + bhq) * Q_;
        am[sidx + qi0]     = m0r;  al[sidx + qi0]     = l0r;
        am[sidx + qi0 + 8] = m1r;  al[sidx + qi0 + 8] = l1r;
    }
}

// merge the four attention splits -> ctx fp16 [b][qi][h][d]
__global__ __launch_bounds__(128) void attn_merge(
    const float* __restrict__ actx, const float* __restrict__ am,
    const float* __restrict__ al, __half* __restrict__ ctxh)
{
    const int bh = blockIdx.x;
    const int b = bh >> 5, h = bh & 31;
    const int d = threadIdx.x;
    const int q0 = blockIdx.y << 2;
    const int NBH = B_ * NH_;

    #pragma unroll
    for (int k = 0; k < 4; k++) {
        const int qi = q0 + k;
        float ms[4], ls[4];
        #pragma unroll
        for (int s = 0; s < 4; s++) {
            ms[s] = am[(s * NBH + bh) * Q_ + qi];
            ls[s] = al[(s * NBH + bh) * Q_ + qi];
        }
        float mm = fmaxf(fmaxf(ms[0], ms[1]), fmaxf(ms[2], ms[3]));
        float ws[4], den = 0.f;
        #pragma unroll
        for (int s = 0; s < 4; s++) { ws[s] = __expf(ms[s] - mm); den += ws[s] * ls[s]; }
        const float inv = 1.0f / den;
        float acc = 0.f;
        #pragma unroll
        for (int s = 0; s < 4; s++)
            acc += ws[s] * actx[((size_t)(s * NBH + bh) * Q_ + qi) * HD_ + d];
        ctxh[((b * Q_ + qi) * NH_ + h) * HD_ + d] = __float2half(acc * inv);
    }
}

// ---------------- launch ----------------
extern "C" void kernel_launch(void* const* d_in, const int* in_sizes, int n_in,
                              void* d_out, int out_size)
{
    const float* hs   = (const float*)d_in[0];
    const float* Wq   = (const float*)d_in[1];
    const float* Wk   = (const float*)d_in[2];
    const float* Wv   = (const float*)d_in[3];
    const float* Wo   = (const float*)d_in[4];
    const float* qlw  = (const float*)d_in[5];
    const float* qlb  = (const float*)d_in[6];
    const float* klw  = (const float*)d_in[7];
    const float* klb  = (const float*)d_in[8];
    const float* pk   = (const float*)d_in[9];
    const float* pv   = (const float*)d_in[10];
    const float* mask = (const float*)d_in[11];
    const int*   pos  = (const int*)d_in[12];
    float* out = (float*)d_out;

    float *qraw, *qraw2, *kraw, *kraw2, *vraw, *vraw2, *actx, *am, *al;
    __half *hsh, *wqt, *wkt, *wvt, *wot, *qhp, *knhp, *vnhp, *khp, *vhtp, *ctxh;
    cudaGetSymbolAddress((void**)&qraw,  g_qraw);
    cudaGetSymbolAddress((void**)&qraw2, g_qraw2);
    cudaGetSymbolAddress((void**)&kraw,  g_kraw);
    cudaGetSymbolAddress((void**)&kraw2, g_kraw2);
    cudaGetSymbolAddress((void**)&vraw,  g_vraw);
    cudaGetSymbolAddress((void**)&vraw2, g_vraw2);
    cudaGetSymbolAddress((void**)&hsh,   g_hsh);
    cudaGetSymbolAddress((void**)&wqt,   g_wqt);
    cudaGetSymbolAddress((void**)&wkt,   g_wkt);
    cudaGetSymbolAddress((void**)&wvt,   g_wvt);
    cudaGetSymbolAddress((void**)&wot,   g_wot);
    cudaGetSymbolAddress((void**)&qhp,   g_qh);
    cudaGetSymbolAddress((void**)&knhp,  g_knh);
    cudaGetSymbolAddress((void**)&vnhp,  g_vnh);
    cudaGetSymbolAddress((void**)&khp,   g_kh);
    cudaGetSymbolAddress((void**)&vhtp,  g_vht);
    cudaGetSymbolAddress((void**)&ctxh,  g_ctxh);
    cudaGetSymbolAddress((void**)&actx,  g_actx);
    cudaGetSymbolAddress((void**)&am,    g_am);
    cudaGetSymbolAddress((void**)&al,    g_al);

    cudaFuncSetAttribute(attn_kernel8, cudaFuncAttributeMaxDynamicSharedMemorySize, ATT8_BYTES);
    cudaFuncSetAttribute(gemm_qkv,     cudaFuncAttributeMaxDynamicSharedMemorySize, GEMMH_SMEM_BYTES);
    cudaFuncSetAttribute(gemm_out,     cudaFuncAttributeMaxDynamicSharedMemorySize, GEMMH_SMEM_BYTES);

    // 0) one-shot fp16 conversions
    cvt_elem<<<(M_ * H_) / (256 * 8), 256>>>(hs, hsh);                       // hidden states
    cvt_wt  <<<dim3(32, 128), 256>>>(Wq, wqt, 4096, 4096);                   // Wq^T
    cvt_wt  <<<dim3(8, 128),  256>>>(Wk, wkt, 1024, 4096);                   // Wk^T
    cvt_wt  <<<dim3(8, 128),  256>>>(Wv, wvt, 1024, 4096);                   // Wv^T
    cvt_wt  <<<dim3(32, 128), 256>>>(Wo, wot, 4096, 4096);                   // Wo^T
    cvt_elem<<<(B_ * KVH_ * P_ * HD_) / (256 * 8), 256>>>(pk, khp);          // past K
    cvt_vt  <<<B_ * KVH_ * (P_ / 32), 256>>>(pv, vhtp);                      // past V (transposed)

    // 1) fused QKV projection (fp16), split-K=2, 3-stage pipe
    gemm_qkv<<<dim3(48, 4, 2), 256, GEMMH_SMEM_BYTES>>>(hsh, wqt, wkt, wvt,
                                                        qraw, kraw, vraw, qraw2, kraw2, vraw2);

    // 2) LN + RoPE + transpose (+ split-K sum), fp16 outputs
    lnrope_kernel<<<M_ * 48, 128>>>(qraw, qraw2, kraw, kraw2, vraw, vraw2,
                                    qlw, qlb, klw, klb, pos, qhp, knhp, vnhp);

    // 3) attention: fp16, 2 heads/CTA (shared KV), 4-way split; merge -> ctx fp16
    attn_kernel8<<<dim3(B_ * 16, 4), 256, ATT8_BYTES>>>(khp, vhtp, mask, qhp, knhp, vnhp,
                                                        actx, am, al);
    attn_merge<<<dim3(B_ * NH_, 16), 128>>>(actx, am, al, ctxh);

    // 4) output projection (fp16 inputs): split-K=2, atomic accumulate
    cudaMemsetAsync(out, 0, (size_t)M_ * H_ * sizeof(float));
    gemm_out<<<dim3(32, 4, 2), 256, GEMMH_SMEM_BYTES>>>(ctxh, wot, out);
}

// round 17
// speedup vs baseline: 1.1200x; 1.0494x over previous
#include <cuda_runtime.h>
#include <cuda_fp16.h>
#include <math.h>

#define B_   4
#define Q_   64
#define H_   4096
#define NH_  32
#define KVH_ 8
#define HD_  128
#define P_   4096
#define M_   256            // B*Q
#define KVLEN 4160          // P+Q
#define QSZ  (M_ * NH_ * HD_)    // 1M
#define KSZ  (M_ * KVH_ * HD_)   // 256K

// ---------------- scratch ----------------
__device__ float g_qraw[4 * QSZ];
__device__ float g_kraw[4 * KSZ];
__device__ float g_vraw[4 * KSZ];
__device__ __half g_hsh[M_ * H_];
__device__ __half g_wqt[H_ * (size_t)H_];
__device__ __half g_wkt[(KVH_ * HD_) * (size_t)H_];
__device__ __half g_wvt[(KVH_ * HD_) * (size_t)H_];
__device__ __half g_wot[H_ * (size_t)H_];
__device__ __half g_qh [B_ * NH_ * Q_ * HD_];
__device__ __half g_knh[B_ * KVH_ * Q_ * HD_];
__device__ __half g_vnh[B_ * KVH_ * HD_ * Q_];
__device__ __half g_kh [B_ * KVH_ * P_ * HD_];
__device__ __half g_vht[B_ * KVH_ * HD_ * P_];
__device__ __half g_ctxh[M_ * NH_ * HD_];
__device__ float g_actx[4 * B_ * NH_ * Q_ * HD_];
__device__ float g_am  [4 * B_ * NH_ * Q_];
__device__ float g_al  [4 * B_ * NH_ * Q_];

// ---------------- helpers ----------------
__device__ __forceinline__ void mma_f16(float& c0, float& c1, float& c2, float& c3,
                                        unsigned a0, unsigned a1, unsigned a2, unsigned a3,
                                        unsigned b0, unsigned b1) {
    asm volatile(
        "mma.sync.aligned.m16n8k16.row.col.f32.f16.f16.f32 "
        "{%0,%1,%2,%3}, {%4,%5,%6,%7}, {%8,%9}, {%0,%1,%2,%3};\n"
        : "+f"(c0), "+f"(c1), "+f"(c2), "+f"(c3)
        : "r"(a0), "r"(a1), "r"(a2), "r"(a3), "r"(b0), "r"(b1));
}

__device__ __forceinline__ void cp16(void* smem_dst, const void* gmem_src) {
    unsigned ds = (unsigned)__cvta_generic_to_shared(smem_dst);
    asm volatile("cp.async.cg.shared.global [%0], [%1], 16;\n" :: "r"(ds), "l"(gmem_src));
}
__device__ __forceinline__ unsigned pack_h2(float a, float b) {
    __half2 h = __floats2half2_rn(a, b);
    return *(unsigned*)&h;
}

// ================= fp16 GEMM: BM64 x BN128 x BK32, 256 thr, 3-stage, m16n8k16 =================
#define HA_S 40
#define HB_S 40
#define H_STAGE (64 * HA_S + 128 * HB_S)
#define GEMMH_SMEM_BYTES (3 * H_STAGE * 2)

template<bool ATOMIC>
__device__ __forceinline__ void gemm_h(
    const __half* __restrict__ A, int lda,
    const __half* __restrict__ Wt, int ldw,
    float* __restrict__ C, int N, int kLen, int m0, int n0, __half* sm)
{
    __half* sAs[3] = { sm, sm + H_STAGE, sm + 2 * H_STAGE };
    __half* sBs[3] = { sm + 64 * HA_S, sm + H_STAGE + 64 * HA_S,
                       sm + 2 * H_STAGE + 64 * HA_S };

    const int tid = threadIdx.x;
    const int warp = tid >> 5, lane = tid & 31;
    const int mw = warp >> 2, nw = warp & 3;
    const int g = lane >> 2, t = lane & 3;
    const int t2 = t << 1;

    const int arow = tid >> 2, acb = (tid & 3) << 3;
    const int brow = tid >> 1, bcb = (tid & 1) << 4;

    const __half* Abase = A + (size_t)m0 * lda;
    const __half* Wbase = Wt + (size_t)n0 * ldw;

    float acc[2][4][4];
    #pragma unroll
    for (int mt = 0; mt < 2; mt++)
        #pragma unroll
        for (int nt = 0; nt < 4; nt++)
            #pragma unroll
            for (int i = 0; i < 4; i++) acc[mt][nt][i] = 0.f;

    const int ntiles = kLen >> 5;

    #define GISSUE(k0, sA, sB) do { \
        cp16((sA) + arow * HA_S + acb, Abase + (size_t)arow * lda + (k0) + acb); \
        cp16((sB) + brow * HB_S + bcb,     Wbase + (size_t)brow * ldw + (k0) + bcb); \
        cp16((sB) + brow * HB_S + bcb + 8, Wbase + (size_t)brow * ldw + (k0) + bcb + 8); \
        asm volatile("cp.async.commit_group;\n"); \
    } while (0)

    GISSUE(0,  sAs[0], sBs[0]);
    GISSUE(32, sAs[1], sBs[1]);

    for (int tI = 0; tI < ntiles; tI++) {
        if (tI + 2 < ntiles) {
            GISSUE((tI + 2) << 5, sAs[(tI + 2) % 3], sBs[(tI + 2) % 3]);
            asm volatile("cp.async.wait_group 2;\n");
        } else if (tI + 1 < ntiles) {
            asm volatile("cp.async.wait_group 1;\n");
        } else {
            asm volatile("cp.async.wait_group 0;\n");
        }
        __syncthreads();

        __half* sA = sAs[tI % 3];
        __half* sB = sBs[tI % 3];

        #pragma unroll
        for (int ks = 0; ks < 2; ks++) {
            const int k0 = ks << 4;
            unsigned a[2][4], b[4][2];
            #pragma unroll
            for (int mt = 0; mt < 2; mt++) {
                const int r = (mw << 5) + (mt << 4) + g;
                a[mt][0] = *(const unsigned*)&sA[r * HA_S + k0 + t2];
                a[mt][1] = *(const unsigned*)&sA[(r + 8) * HA_S + k0 + t2];
                a[mt][2] = *(const unsigned*)&sA[r * HA_S + k0 + 8 + t2];
                a[mt][3] = *(const unsigned*)&sA[(r + 8) * HA_S + k0 + 8 + t2];
            }
            #pragma unroll
            for (int nt = 0; nt < 4; nt++) {
                const int cn = (nw << 5) + (nt << 3) + g;
                b[nt][0] = *(const unsigned*)&sB[cn * HB_S + k0 + t2];
                b[nt][1] = *(const unsigned*)&sB[cn * HB_S + k0 + 8 + t2];
            }
            #pragma unroll
            for (int mt = 0; mt < 2; mt++)
                #pragma unroll
                for (int nt = 0; nt < 4; nt++)
                    mma_f16(acc[mt][nt][0], acc[mt][nt][1], acc[mt][nt][2], acc[mt][nt][3],
                            a[mt][0], a[mt][1], a[mt][2], a[mt][3], b[nt][0], b[nt][1]);
        }
        __syncthreads();
    }
    #undef GISSUE

    #pragma unroll
    for (int mt = 0; mt < 2; mt++) {
        const int r = m0 + (mw << 5) + (mt << 4) + g;
        #pragma unroll
        for (int nt = 0; nt < 4; nt++) {
            const int cn = n0 + (nw << 5) + (nt << 3) + (t << 1);
            if (ATOMIC) {
                atomicAdd(C + r * N + cn,           acc[mt][nt][0]);
                atomicAdd(C + r * N + cn + 1,       acc[mt][nt][1]);
                atomicAdd(C + (r + 8) * N + cn,     acc[mt][nt][2]);
                atomicAdd(C + (r + 8) * N + cn + 1, acc[mt][nt][3]);
            } else {
                *(float2*)(C + r * N + cn)       = make_float2(acc[mt][nt][0], acc[mt][nt][1]);
                *(float2*)(C + (r + 8) * N + cn) = make_float2(acc[mt][nt][2], acc[mt][nt][3]);
            }
        }
    }
}

// fused QKV projection (fp16), split-K = 4 (partials summed in lnrope)
__global__ __launch_bounds__(256, 2) void gemm_qkv(
    const __half* __restrict__ hsh,
    const __half* __restrict__ wqt, const __half* __restrict__ wkt, const __half* __restrict__ wvt,
    float* __restrict__ qraw, float* __restrict__ kraw, float* __restrict__ vraw)
{
    extern __shared__ __half smh[];
    const int x = blockIdx.x;
    const int kw = blockIdx.z;           // 0..3
    const __half* Wt; float* C; int N, nb;
    if (x < 32)      { Wt = wqt; C = qraw + kw * QSZ; N = 4096; nb = x; }
    else if (x < 40) { Wt = wkt; C = kraw + kw * KSZ; N = 1024; nb = x - 32; }
    else             { Wt = wvt; C = vraw + kw * KSZ; N = 1024; nb = x - 40; }
    gemm_h<false>(hsh + kw * 1024, H_, Wt + kw * 1024, H_, C, N, 1024,
                  blockIdx.y << 6, nb << 7, smh);
}

// out projection (fp16), split-K = 2, atomic accumulate into pre-zeroed out
__global__ __launch_bounds__(256, 2) void gemm_out(
    const __half* __restrict__ ctxh, const __half* __restrict__ wot, float* __restrict__ out)
{
    extern __shared__ __half smh[];
    const int kw = blockIdx.z;
    const int KH = (NH_ * HD_) / 2;
    gemm_h<true>(ctxh + kw * KH, NH_ * HD_, wot + kw * KH, NH_ * HD_, out,
                 H_, KH, blockIdx.y << 6, blockIdx.x << 7, smh);
}

// ---------------- fused one-shot fp16 conversion mega-kernel ----------------
// block ranges: [0,512) hs | [512,4608) Wq^T | [4608,5632) Wk^T | [5632,6656) Wv^T |
//               [6656,10752) Wo^T | [10752,18944) pastK | [18944,23040) pastV^T
__device__ __forceinline__ void cvt_elem_body(const float* src, __half* dst, int blk)
{
    const size_t i = ((size_t)blk * 256 + threadIdx.x) << 3;
    const float4 a = *(const float4*)(src + i);
    const float4 b = *(const float4*)(src + i + 4);
    *(uint4*)(dst + i) = make_uint4(pack_h2(a.x, a.y), pack_h2(a.z, a.w),
                                    pack_h2(b.x, b.y), pack_h2(b.z, b.w));
}

__device__ __forceinline__ void cvt_wt_body(const float* src, __half* dst, int N, int K, int blk,
                                            float (*tile)[132])
{
    const int nblk = N >> 7;
    const int n0 = (blk % nblk) << 7, k0 = (blk / nblk) << 5;
    const int tid = threadIdx.x;

    const int row = tid >> 3, cb = (tid & 7) << 4;
    #pragma unroll
    for (int j = 0; j < 4; j++)
        *(float4*)&tile[row][cb + (j << 2)] =
            *(const float4*)(src + (size_t)(k0 + row) * N + n0 + cb + (j << 2));
    __syncthreads();

    const int n = tid >> 1, ks = (tid & 1) << 4;
    __half h[16];
    #pragma unroll
    for (int j = 0; j < 16; j++) h[j] = __float2half(tile[ks + j][n]);
    __half* dstp = dst + (size_t)(n0 + n) * K + k0 + ks;
    *(uint4*)(dstp)     = *(uint4*)&h[0];
    *(uint4*)(dstp + 8) = *(uint4*)&h[8];
}

__global__ __launch_bounds__(256) void cvt_all(
    const float* __restrict__ hs, const float* __restrict__ Wq,
    const float* __restrict__ Wk, const float* __restrict__ Wv,
    const float* __restrict__ Wo, const float* __restrict__ pk,
    const float* __restrict__ pv,
    __half* __restrict__ hsh, __half* __restrict__ wqt, __half* __restrict__ wkt,
    __half* __restrict__ wvt, __half* __restrict__ wot,
    __half* __restrict__ kh, __half* __restrict__ vt)
{
    __shared__ float tile[32][132];
    const int bx = blockIdx.x;
    if (bx < 512) {
        cvt_elem_body(hs, hsh, bx);
    } else if (bx < 4608) {
        cvt_wt_body(Wq, wqt, 4096, 4096, bx - 512, tile);
    } else if (bx < 5632) {
        cvt_wt_body(Wk, wkt, 1024, 4096, bx - 4608, tile);
    } else if (bx < 6656) {
        cvt_wt_body(Wv, wvt, 1024, 4096, bx - 5632, tile);
    } else if (bx < 10752) {
        cvt_wt_body(Wo, wot, 4096, 4096, bx - 6656, tile);
    } else if (bx < 18944) {
        cvt_elem_body(pk, kh, bx - 10752);
    } else {
        const int idx = bx - 18944;
        const int bk  = idx >> 7;
        const int key0 = (idx & 127) << 5;
        const int tid = threadIdx.x;
        const float* src = pv + ((size_t)bk * P_ + key0) * HD_;
        const int row = tid >> 3, cb = (tid & 7) << 4;
        #pragma unroll
        for (int j = 0; j < 4; j++)
            *(float4*)&tile[row][cb + (j << 2)] = *(const float4*)(src + row * HD_ + cb + (j << 2));
        __syncthreads();
        const int d = tid >> 1, ks = (tid & 1) << 4;
        __half h[16];
        #pragma unroll
        for (int j = 0; j < 16; j++) h[j] = __float2half(tile[ks + j][d]);
        __half* dstp = vt + ((size_t)bk * HD_ + d) * P_ + key0 + ks;
        *(uint4*)(dstp)     = *(uint4*)&h[0];
        *(uint4*)(dstp + 8) = *(uint4*)&h[8];
    }
}

// ---------------- LN + RoPE + transpose (sums 4 split-K partials, emits fp16) ----------------
__global__ __launch_bounds__(128) void lnrope_kernel(
    const float* __restrict__ qraw, const float* __restrict__ kraw, const float* __restrict__ vraw,
    const float* __restrict__ qlw, const float* __restrict__ qlb,
    const float* __restrict__ klw, const float* __restrict__ klb,
    const int* __restrict__ pos_ids,
    __half* __restrict__ qout, __half* __restrict__ knout, __half* __restrict__ vnout)
{
    const int blk = blockIdx.x;
    const int bq = blk / 48;
    const int t  = blk - bq * 48;
    const int b  = bq >> 6, qi = bq & 63;
    const int d  = threadIdx.x;

    if (t >= 40) {
        const int vh = t - 40;
        const int i = bq * (KVH_ * HD_) + vh * HD_ + d;
        const float v = vraw[i] + vraw[i + KSZ] + vraw[i + 2 * KSZ] + vraw[i + 3 * KSZ];
        vnout[((b * KVH_ + vh) * HD_ + d) * Q_ + qi] = __float2half(v);
        return;
    }

    __shared__ float row[128];
    __shared__ float red[4];

    float x, w, bb;
    const bool isq = (t < 32);
    if (isq) {
        const int i = bq * (NH_ * HD_) + t * HD_ + d;
        x  = qraw[i] + qraw[i + QSZ] + qraw[i + 2 * QSZ] + qraw[i + 3 * QSZ];
        w  = qlw[t * HD_ + d];
        bb = qlb[t * HD_ + d];
    } else {
        const int kh = t - 32;
        const int i = bq * (KVH_ * HD_) + kh * HD_ + d;
        x  = kraw[i] + kraw[i + KSZ] + kraw[i + 2 * KSZ] + kraw[i + 3 * KSZ];
        w  = klw[kh * HD_ + d];
        bb = klb[kh * HD_ + d];
    }

    const int lane = d & 31, wid = d >> 5;

    float s = x;
    #pragma unroll
    for (int o = 16; o; o >>= 1) s += __shfl_xor_sync(0xffffffffu, s, o);
    if (lane == 0) red[wid] = s;
    __syncthreads();
    const float mean = (red[0] + red[1] + red[2] + red[3]) * (1.f / 128.f);
    const float dx = x - mean;
    float s2 = dx * dx;
    __syncthreads();
    #pragma unroll
    for (int o = 16; o; o >>= 1) s2 += __shfl_xor_sync(0xffffffffu, s2, o);
    if (lane == 0) red[wid] = s2;
    __syncthreads();
    const float var = (red[0] + red[1] + red[2] + red[3]) * (1.f / 128.f);

    const float xn = dx * rsqrtf(var + 1e-5f) * w + bb;
    row[d] = xn;
    __syncthreads();
    const float partner = row[d ^ 64];

    const int j = d & 63;
    const float inv = (float)exp(-(double)(2 * j) * (1.0 / 128.0) * 9.210340371976184);
    const float ang = (float)pos_ids[b * Q_ + qi] * inv;
    const float c = cosf(ang), sn = sinf(ang);
    const float rot = (d < 64) ? -partner : partner;
    const float outv = xn * c + rot * sn;

    if (isq)
        qout[((b * NH_ + t) * Q_ + qi) * HD_ + d] = __float2half(outv * 0.08838834764831845f);
    else
        knout[((b * KVH_ + (t - 32)) * Q_ + qi) * HD_ + d] = __float2half(outv);
}

// ---------------- flash attention v8 (R16): fp16, 2 q-heads/CTA, 4-way KV split ----------------
#define CHK   32
#define SQ_H  136
#define SK_H  136
#define SVT_H 40
#define SP_H  40
#define POFF_Q   0
#define POFF_K0  (128 * SQ_H)
#define POFF_K1  (POFF_K0 + CHK * SK_H)
#define POFF_V0  (POFF_K1 + CHK * SK_H)
#define POFF_V1  (POFF_V0 + HD_ * SVT_H)
#define POFF_S   (POFF_V1 + HD_ * SVT_H)
#define ATT8_HALFS (POFF_S + 128 * SP_H)
#define ATT8_BYTES (ATT8_HALFS * 2)

__global__ __launch_bounds__(256, 2) void attn_kernel8(
    const __half* __restrict__ kh, const __half* __restrict__ vht,
    const float* __restrict__ mask,
    const __half* __restrict__ qh, const __half* __restrict__ knh,
    const __half* __restrict__ vnh,
    float* __restrict__ actx, float* __restrict__ am, float* __restrict__ al)
{
    extern __shared__ __half smh[];
    __half* sQ  = smh + POFF_Q;
    __half* sKb[2] = { smh + POFF_K0, smh + POFF_K1 };
    __half* sVb[2] = { smh + POFF_V0, smh + POFF_V1 };
    __half* sS  = smh + POFF_S;

    const int tid = threadIdx.x;
    const int bp = blockIdx.x;
    const int split = blockIdx.y;
    const int b = bp >> 4;
    const int h0 = (bp & 15) << 1;
    const int kvh = h0 >> 2;

    const int warp = tid >> 5, lane = tid & 31;
    const int g = lane >> 2, t = lane & 3;
    const int r0 = (warp << 4) + g;
    const int t2 = t << 1;
    const int hq = h0 + (r0 >> 6);
    const int qi0 = r0 & 63;

    const int krow = tid >> 3, kcb = (tid & 7) << 4;
    const int vrow = tid >> 1, vcb = (tid & 1) << 4;

    {
        #pragma unroll
        for (int i = 0; i < 8; i++) {
            const int idx = tid + (i << 8);
            const int row = idx >> 4, col = (idx & 15) << 3;
            const int hh = h0 + (row >> 6), qq = row & 63;
            *(uint4*)(sQ + row * SQ_H + col) =
                *(const uint4*)(qh + ((size_t)(b * NH_ + hh) * Q_ + qq) * HD_ + col);
        }
    }

    float m0r = -1e30f, m1r = -1e30f, l0r = 0.f, l1r = 0.f;

    float o[16][4];
    #pragma unroll
    for (int nt = 0; nt < 16; nt++)
        #pragma unroll
        for (int i = 0; i < 4; i++) o[nt][i] = 0.f;

    const int keybase0 = (split <= 1) ? split * 1056 : 2112 + (split - 2) * 1024;
    const int nchk = (split <= 1) ? 33 : 32;
    const size_t kbase_past = (size_t)(b * KVH_ + kvh) * P_ * HD_;
    const size_t kbase_new  = (size_t)(b * KVH_ + kvh) * Q_ * HD_;
    const size_t vbase_past = (size_t)(b * KVH_ + kvh) * HD_ * P_;
    const size_t vbase_new  = (size_t)(b * KVH_ + kvh) * HD_ * Q_;

    {
        const int base = keybase0;
        const __half* Kc = (base < P_) ? kh + kbase_past + (size_t)base * HD_
                                       : knh + kbase_new + (size_t)(base - P_) * HD_;
        const __half* Vc; int vstride;
        if (base < P_) { Vc = vht + vbase_past + base; vstride = P_; }
        else           { Vc = vnh + vbase_new + (base - P_); vstride = Q_; }
        cp16(sKb[0] + krow * SK_H + kcb,     Kc + krow * HD_ + kcb);
        cp16(sKb[0] + krow * SK_H + kcb + 8, Kc + krow * HD_ + kcb + 8);
        cp16(sVb[0] + vrow * SVT_H + vcb,     Vc + (size_t)vrow * vstride + vcb);
        cp16(sVb[0] + vrow * SVT_H + vcb + 8, Vc + (size_t)vrow * vstride + vcb + 8);
        asm volatile("cp.async.commit_group;\n");
    }

    __syncthreads();
    unsigned qa[8][4];
    #pragma unroll
    for (int ks = 0; ks < 8; ks++) {
        const int k0 = ks << 4;
        qa[ks][0] = *(const unsigned*)&sQ[r0 * SQ_H + k0 + t2];
        qa[ks][1] = *(const unsigned*)&sQ[(r0 + 8) * SQ_H + k0 + t2];
        qa[ks][2] = *(const unsigned*)&sQ[r0 * SQ_H + k0 + 8 + t2];
        qa[ks][3] = *(const unsigned*)&sQ[(r0 + 8) * SQ_H + k0 + 8 + t2];
    }

    for (int chunk = 0; chunk < nchk; chunk++) {
        if (chunk + 1 < nchk) {
            const int base = keybase0 + (chunk + 1) * CHK;
            const __half* Kc = (base < P_) ? kh + kbase_past + (size_t)base * HD_
                                           : knh + kbase_new + (size_t)(base - P_) * HD_;
            const __half* Vc; int vstride;
            if (base < P_) { Vc = vht + vbase_past + base; vstride = P_; }
            else           { Vc = vnh + vbase_new + (base - P_); vstride = Q_; }
            __half* dK = sKb[(chunk + 1) & 1];
            __half* dV = sVb[(chunk + 1) & 1];
            cp16(dK + krow * SK_H + kcb,     Kc + krow * HD_ + kcb);
            cp16(dK + krow * SK_H + kcb + 8, Kc + krow * HD_ + kcb + 8);
            cp16(dV + vrow * SVT_H + vcb,     Vc + (size_t)vrow * vstride + vcb);
            cp16(dV + vrow * SVT_H + vcb + 8, Vc + (size_t)vrow * vstride + vcb + 8);
            asm volatile("cp.async.commit_group;\n");
            asm volatile("cp.async.wait_group 1;\n");
        } else {
            asm volatile("cp.async.wait_group 0;\n");
        }
        __syncthreads();

        __half* sK = sKb[chunk & 1];
        __half* sV = sVb[chunk & 1];

        float sc[4][4];
        #pragma unroll
        for (int nt = 0; nt < 4; nt++)
            #pragma unroll
            for (int i = 0; i < 4; i++) sc[nt][i] = 0.f;

        #pragma unroll
        for (int ks = 0; ks < 8; ks++) {
            const int k0 = ks << 4;
            #pragma unroll
            for (int nt = 0; nt < 4; nt++) {
                const int cn = (nt << 3) + g;
                unsigned b0 = *(const unsigned*)&sK[cn * SK_H + k0 + t2];
                unsigned b1 = *(const unsigned*)&sK[cn * SK_H + k0 + 8 + t2];
                mma_f16(sc[nt][0], sc[nt][1], sc[nt][2], sc[nt][3],
                        qa[ks][0], qa[ks][1], qa[ks][2], qa[ks][3], b0, b1);
            }
        }

        const int base = keybase0 + chunk * CHK;
        if (base >= P_) {
            const float* mr0 = mask + (b * Q_ + qi0) * KVLEN + base;
            const float* mr1 = mask + (b * Q_ + qi0 + 8) * KVLEN + base;
            #pragma unroll
            for (int nt = 0; nt < 4; nt++) {
                const float2 mv0 = *(const float2*)(mr0 + (nt << 3) + t2);
                const float2 mv1 = *(const float2*)(mr1 + (nt << 3) + t2);
                sc[nt][0] += mv0.x; sc[nt][1] += mv0.y;
                sc[nt][2] += mv1.x; sc[nt][3] += mv1.y;
            }
        }

        float cm0 = -1e30f, cm1 = -1e30f;
        #pragma unroll
        for (int nt = 0; nt < 4; nt++) {
            cm0 = fmaxf(cm0, fmaxf(sc[nt][0], sc[nt][1]));
            cm1 = fmaxf(cm1, fmaxf(sc[nt][2], sc[nt][3]));
        }
        cm0 = fmaxf(cm0, __shfl_xor_sync(0xffffffffu, cm0, 1));
        cm0 = fmaxf(cm0, __shfl_xor_sync(0xffffffffu, cm0, 2));
        cm1 = fmaxf(cm1, __shfl_xor_sync(0xffffffffu, cm1, 1));
        cm1 = fmaxf(cm1, __shfl_xor_sync(0xffffffffu, cm1, 2));

        const float mn0 = fmaxf(m0r, cm0);
        const float mn1 = fmaxf(m1r, cm1);
        const float scl0 = __expf(m0r - mn0);
        const float scl1 = __expf(m1r - mn1);

        float sum0 = 0.f, sum1 = 0.f;
        #pragma unroll
        for (int nt = 0; nt < 4; nt++) {
            float p;
            p = __expf(sc[nt][0] - mn0); sc[nt][0] = p; sum0 += p;
            p = __expf(sc[nt][1] - mn0); sc[nt][1] = p; sum0 += p;
            p = __expf(sc[nt][2] - mn1); sc[nt][2] = p; sum1 += p;
            p = __expf(sc[nt][3] - mn1); sc[nt][3] = p; sum1 += p;
        }
        sum0 += __shfl_xor_sync(0xffffffffu, sum0, 1);
        sum0 += __shfl_xor_sync(0xffffffffu, sum0, 2);
        sum1 += __shfl_xor_sync(0xffffffffu, sum1, 1);
        sum1 += __shfl_xor_sync(0xffffffffu, sum1, 2);

        l0r = l0r * scl0 + sum0;  m0r = mn0;
        l1r = l1r * scl1 + sum1;  m1r = mn1;

        #pragma unroll
        for (int nt = 0; nt < 16; nt++) {
            o[nt][0] *= scl0; o[nt][1] *= scl0;
            o[nt][2] *= scl1; o[nt][3] *= scl1;
        }

        #pragma unroll
        for (int nt = 0; nt < 4; nt++) {
            *(unsigned*)&sS[r0 * SP_H + (nt << 3) + t2]       = pack_h2(sc[nt][0], sc[nt][1]);
            *(unsigned*)&sS[(r0 + 8) * SP_H + (nt << 3) + t2] = pack_h2(sc[nt][2], sc[nt][3]);
        }
        __syncwarp();

        #pragma unroll
        for (int kk = 0; kk < 2; kk++) {
            const int k0 = kk << 4;
            unsigned a0 = *(const unsigned*)&sS[r0 * SP_H + k0 + t2];
            unsigned a1 = *(const unsigned*)&sS[(r0 + 8) * SP_H + k0 + t2];
            unsigned a2 = *(const unsigned*)&sS[r0 * SP_H + k0 + 8 + t2];
            unsigned a3 = *(const unsigned*)&sS[(r0 + 8) * SP_H + k0 + 8 + t2];
            #pragma unroll
            for (int nt = 0; nt < 16; nt++) {
                const int cn = (nt << 3) + g;
                unsigned b0 = *(const unsigned*)&sV[cn * SVT_H + k0 + t2];
                unsigned b1 = *(const unsigned*)&sV[cn * SVT_H + k0 + 8 + t2];
                mma_f16(o[nt][0], o[nt][1], o[nt][2], o[nt][3], a0, a1, a2, a3, b0, b1);
            }
        }
        __syncthreads();
    }

    const int bhq = b * NH_ + hq;
    float* abase = actx + ((size_t)(split * (B_ * NH_) + bhq) * Q_) * HD_;
    #pragma unroll
    for (int nt = 0; nt < 16; nt++) {
        const int cn = (nt << 3) + t2;
        *(float2*)(abase + qi0 * HD_ + cn)       = make_float2(o[nt][0], o[nt][1]);
        *(float2*)(abase + (qi0 + 8) * HD_ + cn) = make_float2(o[nt][2], o[nt][3]);
    }
    if (t == 0) {
        const int sidx = (split * (B_ * NH_) + bhq) * Q_;
        am[sidx + qi0]     = m0r;  al[sidx + qi0]     = l0r;
        am[sidx + qi0 + 8] = m1r;  al[sidx + qi0 + 8] = l1r;
    }
}

// merge the four attention splits -> ctx fp16 [b][qi][h][d]
__global__ __launch_bounds__(128) void attn_merge(
    const float* __restrict__ actx, const float* __restrict__ am,
    const float* __restrict__ al, __half* __restrict__ ctxh)
{
    const int bh = blockIdx.x;
    const int b = bh >> 5, h = bh & 31;
    const int d = threadIdx.x;
    const int q0 = blockIdx.y << 2;
    const int NBH = B_ * NH_;

    #pragma unroll
    for (int k = 0; k < 4; k++) {
        const int qi = q0 + k;
        float ms[4], ls[4];
        #pragma unroll
        for (int s = 0; s < 4; s++) {
            ms[s] = am[(s * NBH + bh) * Q_ + qi];
            ls[s] = al[(s * NBH + bh) * Q_ + qi];
        }
        float mm = fmaxf(fmaxf(ms[0], ms[1]), fmaxf(ms[2], ms[3]));
        float ws[4], den = 0.f;
        #pragma unroll
        for (int s = 0; s < 4; s++) { ws[s] = __expf(ms[s] - mm); den += ws[s] * ls[s]; }
        const float inv = 1.0f / den;
        float acc = 0.f;
        #pragma unroll
        for (int s = 0; s < 4; s++)
            acc += ws[s] * actx[((size_t)(s * NBH + bh) * Q_ + qi) * HD_ + d];
        ctxh[((b * Q_ + qi) * NH_ + h) * HD_ + d] = __float2half(acc * inv);
    }
}

// ---------------- launch ----------------
extern "C" void kernel_launch(void* const* d_in, const int* in_sizes, int n_in,
                              void* d_out, int out_size)
{
    const float* hs   = (const float*)d_in[0];
    const float* Wq   = (const float*)d_in[1];
    const float* Wk   = (const float*)d_in[2];
    const float* Wv   = (const float*)d_in[3];
    const float* Wo   = (const float*)d_in[4];
    const float* qlw  = (const float*)d_in[5];
    const float* qlb  = (const float*)d_in[6];
    const float* klw  = (const float*)d_in[7];
    const float* klb  = (const float*)d_in[8];
    const float* pk   = (const float*)d_in[9];
    const float* pv   = (const float*)d_in[10];
    const float* mask = (const float*)d_in[11];
    const int*   pos  = (const int*)d_in[12];
    float* out = (float*)d_out;

    float *qraw, *kraw, *vraw, *actx, *am, *al;
    __half *hsh, *wqt, *wkt, *wvt, *wot, *qhp, *knhp, *vnhp, *khp, *vhtp, *ctxh;
    cudaGetSymbolAddress((void**)&qraw,  g_qraw);
    cudaGetSymbolAddress((void**)&kraw,  g_kraw);
    cudaGetSymbolAddress((void**)&vraw,  g_vraw);
    cudaGetSymbolAddress((void**)&hsh,   g_hsh);
    cudaGetSymbolAddress((void**)&wqt,   g_wqt);
    cudaGetSymbolAddress((void**)&wkt,   g_wkt);
    cudaGetSymbolAddress((void**)&wvt,   g_wvt);
    cudaGetSymbolAddress((void**)&wot,   g_wot);
    cudaGetSymbolAddress((void**)&qhp,   g_qh);
    cudaGetSymbolAddress((void**)&knhp,  g_knh);
    cudaGetSymbolAddress((void**)&vnhp,  g_vnh);
    cudaGetSymbolAddress((void**)&khp,   g_kh);
    cudaGetSymbolAddress((void**)&vhtp,  g_vht);
    cudaGetSymbolAddress((void**)&ctxh,  g_ctxh);
    cudaGetSymbolAddress((void**)&actx,  g_actx);
    cudaGetSymbolAddress((void**)&am,    g_am);
    cudaGetSymbolAddress((void**)&al,    g_al);

    cudaFuncSetAttribute(attn_kernel8, cudaFuncAttributeMaxDynamicSharedMemorySize, ATT8_BYTES);
    cudaFuncSetAttribute(gemm_qkv,     cudaFuncAttributeMaxDynamicSharedMemorySize, GEMMH_SMEM_BYTES);
    cudaFuncSetAttribute(gemm_out,     cudaFuncAttributeMaxDynamicSharedMemorySize, GEMMH_SMEM_BYTES);

    // 0) fused one-shot fp16 conversions (hs, 4 weights transposed, past K, past V^T)
    cvt_all<<<23040, 256>>>(hs, Wq, Wk, Wv, Wo, pk, pv,
                            hsh, wqt, wkt, wvt, wot, khp, vhtp);

    // 1) fused QKV projection (fp16), split-K=4, 3-stage pipe
    gemm_qkv<<<dim3(48, 4, 4), 256, GEMMH_SMEM_BYTES>>>(hsh, wqt, wkt, wvt, qraw, kraw, vraw);

    // 2) LN + RoPE + transpose (+ 4-way split-K sum), fp16 outputs
    lnrope_kernel<<<M_ * 48, 128>>>(qraw, kraw, vraw, qlw, qlb, klw, klb, pos,
                                    qhp, knhp, vnhp);

    // 3) attention: fp16, 2 heads/CTA (shared KV), 4-way split; merge -> ctx fp16
    attn_kernel8<<<dim3(B_ * 16, 4), 256, ATT8_BYTES>>>(khp, vhtp, mask, qhp, knhp, vnhp,
                                                        actx, am, al);
    attn_merge<<<dim3(B_ * NH_, 16), 128>>>(actx, am, al, ctxh);

    // 4) output projection (fp16 inputs): split-K=2, atomic accumulate
    cudaMemsetAsync(out, 0, (size_t)M_ * H_ * sizeof(float));
    gemm_out<<<dim3(32, 4, 2), 256, GEMMH_SMEM_BYTES>>>(ctxh, wot, out);
}